// round 13
// baseline (speedup 1.0000x reference)
#include <cuda_runtime.h>
#include <cuda_fp16.h>
#include <math.h>
#include <stdint.h>

#define TOKENS   4096
#define DMODEL   1024
#define DINNER   2048
#define DSTATE   16
#define DTRANK   64
#define FFIN     4096
#define LSEQ     2048
#define NDBC     128

// ---------------- scratch ----------------
__device__ __align__(128) __half g_h    [TOKENS * DMODEL];
__device__ __align__(128) float  g_xz   [TOKENS * 2 * DINNER];
__device__ __align__(128) float  g_xc   [TOKENS * DINNER];
__device__ __align__(128) __half g_xch  [TOKENS * DINNER];
__device__ __align__(128) float  g_dbc  [TOKENS * NDBC];
__device__ __align__(128) __half g_dtlo [TOKENS * DTRANK];
__device__ __align__(128) float  g_dt   [TOKENS * DINNER];
__device__ __align__(128) __half g_y    [TOKENS * DINNER];
__device__ __align__(128) float  g_out1 [TOKENS * DMODEL];
__device__ __align__(128) __half g_h2   [TOKENS * DMODEL];
__device__ __align__(128) __half g_pa   [TOKENS * FFIN];   // a-half (fp16)
__device__ __align__(128) __half g_ffa  [TOKENS * FFIN];
__device__ __align__(128) __half g_wtin [4096 * 1024];
__device__ __align__(128) __half g_wtout[1024 * 2048];
__device__ __align__(128) __half g_wtff1[8192 * 1024];
__device__ __align__(128) __half g_wtff2[1024 * 4096];
__device__ __align__(128) __half g_wxt  [128 * 2048];
__device__ __align__(128) __half g_wdtt [2048 * 64];

// ---------------- helpers ----------------
__device__ __forceinline__ float softplus_f(float x) {
    return (x > 20.f) ? x : log1pf(expf(x));
}
__device__ __forceinline__ float tanh_ap(float x) {
    float r;
    asm("tanh.approx.f32 %0, %1;" : "=f"(r) : "f"(x));
    return r;
}
__device__ __forceinline__ float gelu_t(float g) {
    float u = 0.7978845608028654f * fmaf(0.044715f * g * g, g, g);
    return 0.5f * g * (1.f + tanh_ap(u));
}
__device__ __forceinline__ uint32_t smem_u32(const void* p) {
    uint32_t a;
    asm("{ .reg .u64 t; cvta.to.shared.u64 t, %1; cvt.u32.u64 %0, t; }" : "=r"(a) : "l"(p));
    return a;
}
__device__ __forceinline__ void cp16(uint32_t dst, const void* src) {
    asm volatile("cp.async.cg.shared.global [%0], [%1], 16;" :: "r"(dst), "l"(src));
}
#define CP_COMMIT() asm volatile("cp.async.commit_group;" ::: "memory")
#define CP_WAIT0()  asm volatile("cp.async.wait_group 0;" ::: "memory")
#define CP_WAIT1()  asm volatile("cp.async.wait_group 1;" ::: "memory")

__device__ __forceinline__ void ldm_x4(uint32_t& r0, uint32_t& r1,
                                       uint32_t& r2, uint32_t& r3, uint32_t addr)
{
    asm volatile("ldmatrix.sync.aligned.m8n8.x4.shared.b16 {%0,%1,%2,%3}, [%4];"
                 : "=r"(r0), "=r"(r1), "=r"(r2), "=r"(r3) : "r"(addr));
}
__device__ __forceinline__ void mma_f16(
    float& c0, float& c1, float& c2, float& c3,
    uint32_t a0, uint32_t a1, uint32_t a2, uint32_t a3,
    uint32_t b0, uint32_t b1)
{
    asm volatile(
        "mma.sync.aligned.m16n8k16.row.col.f32.f16.f16.f32 "
        "{%0,%1,%2,%3}, {%4,%5,%6,%7}, {%8,%9}, {%0,%1,%2,%3};"
        : "+f"(c0), "+f"(c1), "+f"(c2), "+f"(c3)
        : "r"(a0), "r"(a1), "r"(a2), "r"(a3), "r"(b0), "r"(b1));
}

// ---------------------------------------------------------------------------
// Common GEMM config: 128x128 tile, BK=64 halfs, 8 warps 4(M)x2(N),
// 3-stage cp.async pipeline, one __syncthreads per chunk.
// ---------------------------------------------------------------------------
#define BM 128
#define BN 128
#define BKH 64
#define LDH 72
#define HSTG ((BM + BN) * LDH)
#define MH_SMEM (3 * HSTG * 2)          // 110592 B

__device__ __forceinline__ void mh_load(
    const __half* __restrict__ A, const __half* __restrict__ Bw, int K,
    int m0, int n0, uint32_t sbyte, int stage, int chunk, int tid)
{
    uint32_t ab = sbyte + (uint32_t)stage * (HSTG * 2);
    uint32_t bb = ab + BM * LDH * 2;
    const __half* Ap = A  + (size_t)m0 * K + chunk * BKH;
    const __half* Bp = Bw + (size_t)n0 * K + chunk * BKH;
    #pragma unroll
    for (int p = 0; p < 4; p++) {
        int idx = tid + (p << 8);
        int r = idx >> 3, c = idx & 7;
        cp16(ab + (uint32_t)(r * LDH + c * 8) * 2, Ap + (size_t)r * K + c * 8);
    }
    #pragma unroll
    for (int p = 0; p < 4; p++) {
        int idx = tid + (p << 8);
        int r = idx >> 3, c = idx & 7;
        cp16(bb + (uint32_t)(r * LDH + c * 8) * 2, Bp + (size_t)r * K + c * 8);
    }
}

// mainloop macro body shared by the GEMM variants (accumulates into acc[2][8][4])
#define MH_MAINLOOP(Aptr, Bptr)                                              \
    const int nc = K / BKH;                                                  \
    mh_load(Aptr, Bptr, K, m0, n0, sbyte, 0, 0, tid);                        \
    CP_COMMIT();                                                             \
    if (1 < nc) mh_load(Aptr, Bptr, K, m0, n0, sbyte, 1, 1, tid);            \
    CP_COMMIT();                                                             \
    int stage = 0;                                                           \
    for (int ks = 0; ks < nc; ks++) {                                        \
        if (ks + 1 < nc) { CP_WAIT1(); } else { CP_WAIT0(); }                \
        __syncthreads();                                                     \
        int ldst = stage + 2; if (ldst >= 3) ldst -= 3;                      \
        if (ks + 2 < nc)                                                     \
            mh_load(Aptr, Bptr, K, m0, n0, sbyte, ldst, ks + 2, tid);        \
        CP_COMMIT();                                                         \
        uint32_t as_ = sbyte + (uint32_t)stage * (HSTG * 2);                 \
        uint32_t bs_ = as_ + BM * LDH * 2;                                   \
        _Pragma("unroll")                                                    \
        for (int kk = 0; kk < 4; kk++) {                                     \
            int k = kk * 16;                                                 \
            uint32_t a[2][4];                                                \
            _Pragma("unroll")                                                \
            for (int mt = 0; mt < 2; mt++) {                                 \
                int r = wm * 32 + mt * 16 + a_r;                             \
                ldm_x4(a[mt][0], a[mt][1], a[mt][2], a[mt][3],               \
                       as_ + (uint32_t)(r * LDH + k + a_k) * 2);             \
            }                                                                \
            uint32_t b[8][2];                                                \
            _Pragma("unroll")                                                \
            for (int q = 0; q < 4; q++) {                                    \
                int r = wn * 64 + q * 16 + b_r;                              \
                uint32_t t0, t1, t2, t3;                                     \
                ldm_x4(t0, t1, t2, t3,                                       \
                       bs_ + (uint32_t)(r * LDH + k + b_k) * 2);             \
                b[2 * q][0] = t0;  b[2 * q][1] = t1;                         \
                b[2 * q + 1][0] = t2;  b[2 * q + 1][1] = t3;                 \
            }                                                                \
            _Pragma("unroll")                                                \
            for (int mt = 0; mt < 2; mt++)                                   \
                _Pragma("unroll")                                            \
                for (int nt = 0; nt < 8; nt++)                               \
                    mma_f16(acc[mt][nt][0], acc[mt][nt][1],                  \
                            acc[mt][nt][2], acc[mt][nt][3],                  \
                            a[mt][0], a[mt][1], a[mt][2], a[mt][3],          \
                            b[nt][0], b[nt][1]);                             \
        }                                                                    \
        stage++; if (stage >= 3) stage -= 3;                                 \
    }

#define MH_PREAMBLE                                                          \
    extern __shared__ char smraw[];                                          \
    const uint32_t sbyte = smem_u32(smraw);                                  \
    const int tid  = threadIdx.x;                                            \
    const int lane = tid & 31;                                               \
    const int wid  = tid >> 5;                                               \
    const int wm   = wid >> 1;                                               \
    const int wn   = wid & 1;                                                \
    const int row  = lane >> 2;                                              \
    const int qc   = lane & 3;                                               \
    const int m0 = blockIdx.y * BM;                                          \
    const int n0 = blockIdx.x * BN;                                          \
    const int a_r  = ((lane >> 3) & 1) * 8 + (lane & 7);                     \
    const int a_k  = (lane >> 4) * 8;                                        \
    const int b_r  = (lane >> 4) * 8 + (lane & 7);                           \
    const int b_k  = ((lane >> 3) & 1) * 8;                                  \
    float acc[2][8][4];                                                      \
    _Pragma("unroll")                                                        \
    for (int i = 0; i < 2; i++)                                              \
        _Pragma("unroll")                                                    \
        for (int j = 0; j < 8; j++)                                          \
            _Pragma("unroll")                                                \
            for (int q = 0; q < 4; q++) acc[i][j][q] = 0.f;

// ---------------------------------------------------------------------------
// fp32-out GEMM. MODE bits: 1 = +bias[n], 2 = +res[m,n], 4 = softplus.
// ---------------------------------------------------------------------------
template <int MODE>
__global__ void __launch_bounds__(256, 2) mh_gemm(
    const __half* __restrict__ A, const __half* __restrict__ Bw,
    float* __restrict__ C, const float* __restrict__ bias,
    const float* __restrict__ res, int K, int N)
{
    MH_PREAMBLE
    MH_MAINLOOP(A, Bw)

    #pragma unroll
    for (int mt = 0; mt < 2; mt++) {
        int gr0 = m0 + wm * 32 + mt * 16 + row;
        #pragma unroll
        for (int nt = 0; nt < 8; nt++) {
            int gc = n0 + wn * 64 + nt * 8 + qc * 2;
            float2 v0 = make_float2(acc[mt][nt][0], acc[mt][nt][1]);
            float2 v1 = make_float2(acc[mt][nt][2], acc[mt][nt][3]);
            if (MODE & 1) {
                float2 bb = *(const float2*)(bias + gc);
                v0.x += bb.x; v0.y += bb.y;
                v1.x += bb.x; v1.y += bb.y;
            }
            if (MODE & 4) {
                v0.x = softplus_f(v0.x); v0.y = softplus_f(v0.y);
                v1.x = softplus_f(v1.x); v1.y = softplus_f(v1.y);
            }
            if (MODE & 2) {
                float2 r0 = *(const float2*)(res + (size_t)gr0 * N + gc);
                float2 r1 = *(const float2*)(res + (size_t)(gr0 + 8) * N + gc);
                v0.x += r0.x; v0.y += r0.y;
                v1.x += r1.x; v1.y += r1.y;
            }
            *(float2*)(C + (size_t)gr0 * N + gc)       = v0;
            *(float2*)(C + (size_t)(gr0 + 8) * N + gc) = v1;
        }
    }
}

// ---------------------------------------------------------------------------
// ff1 a-half: pa = h2 @ Wa^T + bias  (fp16 out)
// ---------------------------------------------------------------------------
__global__ void __launch_bounds__(256, 2) mha_gemm(
    const __half* __restrict__ A, const __half* __restrict__ Bw,
    __half* __restrict__ C, const float* __restrict__ bias, int K, int N)
{
    MH_PREAMBLE
    MH_MAINLOOP(A, Bw)

    #pragma unroll
    for (int mt = 0; mt < 2; mt++) {
        int gr0 = m0 + wm * 32 + mt * 16 + row;
        #pragma unroll
        for (int nt = 0; nt < 8; nt++) {
            int gc = n0 + wn * 64 + nt * 8 + qc * 2;
            float2 bb = *(const float2*)(bias + gc);
            ((__half2*)(C + (size_t)gr0 * N))[gc >> 1] =
                __floats2half2_rn(acc[mt][nt][0] + bb.x, acc[mt][nt][1] + bb.y);
            ((__half2*)(C + (size_t)(gr0 + 8) * N))[gc >> 1] =
                __floats2half2_rn(acc[mt][nt][2] + bb.x, acc[mt][nt][3] + bb.y);
        }
    }
}

// ---------------------------------------------------------------------------
// ff1 g-half + geglu: ffa = pa * gelu(h2 @ Wg^T + bias_g)  (fp16 out)
// ---------------------------------------------------------------------------
__global__ void __launch_bounds__(256, 2) mhg_gemm(
    const __half* __restrict__ A, const __half* __restrict__ Bw,
    __half* __restrict__ C, const float* __restrict__ bias,
    const __half* __restrict__ abuf, int K, int N)
{
    MH_PREAMBLE
    MH_MAINLOOP(A, Bw)

    #pragma unroll
    for (int mt = 0; mt < 2; mt++) {
        int gr0 = m0 + wm * 32 + mt * 16 + row;
        #pragma unroll
        for (int nt = 0; nt < 8; nt++) {
            int gc = n0 + wn * 64 + nt * 8 + qc * 2;
            float2 bb = *(const float2*)(bias + gc);
            float2 av0 = __half22float2(((const __half2*)(abuf + (size_t)gr0 * N))[gc >> 1]);
            float2 av1 = __half22float2(((const __half2*)(abuf + (size_t)(gr0 + 8) * N))[gc >> 1]);
            float g0 = acc[mt][nt][0] + bb.x, g1 = acc[mt][nt][1] + bb.y;
            float g2 = acc[mt][nt][2] + bb.x, g3 = acc[mt][nt][3] + bb.y;
            ((__half2*)(C + (size_t)gr0 * N))[gc >> 1] =
                __floats2half2_rn(av0.x * gelu_t(g0), av0.y * gelu_t(g1));
            ((__half2*)(C + (size_t)(gr0 + 8) * N))[gc >> 1] =
                __floats2half2_rn(av1.x * gelu_t(g2), av1.y * gelu_t(g3));
        }
    }
}

// ---------------------------------------------------------------------------
// wx tensor GEMM: dbc[M,128] = xch[M,2048] @ wxt[128,2048]^T  (2-stage)
// ---------------------------------------------------------------------------
#define WXSTG ((64 + 128) * LDH)
#define WX_SMEM (2 * WXSTG * 2)

__device__ __forceinline__ void wx_load(
    const __half* __restrict__ A, const __half* __restrict__ Bw,
    int m0, uint32_t sbyte, int stage, int chunk, int tid)
{
    uint32_t ab = sbyte + (uint32_t)stage * (WXSTG * 2);
    uint32_t bb = ab + 64 * LDH * 2;
    const __half* Ap = A  + (size_t)m0 * DINNER + chunk * BKH;
    const __half* Bp = Bw + chunk * BKH;
    #pragma unroll
    for (int p = 0; p < 2; p++) {
        int idx = tid + (p << 8);
        int r = idx >> 3, c = idx & 7;
        cp16(ab + (uint32_t)(r * LDH + c * 8) * 2, Ap + (size_t)r * DINNER + c * 8);
    }
    #pragma unroll
    for (int p = 0; p < 4; p++) {
        int idx = tid + (p << 8);
        int r = idx >> 3, c = idx & 7;
        cp16(bb + (uint32_t)(r * LDH + c * 8) * 2, Bp + (size_t)r * DINNER + c * 8);
    }
}

__global__ void __launch_bounds__(256, 2) wx_tc(
    const __half* __restrict__ A, const __half* __restrict__ Bw,
    float* __restrict__ dbc, __half* __restrict__ dtlo)
{
    extern __shared__ char smraw[];
    const uint32_t sbyte = smem_u32(smraw);
    const int tid  = threadIdx.x;
    const int lane = tid & 31;
    const int wid  = tid >> 5;
    const int wm   = wid >> 2;
    const int wn   = wid & 3;
    const int row  = lane >> 2;
    const int qc   = lane & 3;
    const int m0 = blockIdx.y * 64;

    const int a_r  = ((lane >> 3) & 1) * 8 + (lane & 7);
    const int a_k  = (lane >> 4) * 8;
    const int b_r  = (lane >> 4) * 8 + (lane & 7);
    const int b_k  = ((lane >> 3) & 1) * 8;

    float acc[2][4][4];
    #pragma unroll
    for (int i = 0; i < 2; i++)
        #pragma unroll
        for (int j = 0; j < 4; j++)
            #pragma unroll
            for (int q = 0; q < 4; q++) acc[i][j][q] = 0.f;

    const int nc = DINNER / BKH;
    wx_load(A, Bw, m0, sbyte, 0, 0, tid);
    CP_COMMIT();

    for (int ks = 0; ks < nc; ks++) {
        if (ks + 1 < nc) {
            wx_load(A, Bw, m0, sbyte, (ks + 1) & 1, ks + 1, tid);
            CP_COMMIT();
            CP_WAIT1();
        } else {
            CP_WAIT0();
        }
        __syncthreads();

        uint32_t as_ = sbyte + (uint32_t)(ks & 1) * (WXSTG * 2);
        uint32_t bs_ = as_ + 64 * LDH * 2;
        #pragma unroll
        for (int kk = 0; kk < 4; kk++) {
            int k = kk * 16;
            uint32_t a[2][4];
            #pragma unroll
            for (int mt = 0; mt < 2; mt++) {
                int r = wm * 32 + mt * 16 + a_r;
                ldm_x4(a[mt][0], a[mt][1], a[mt][2], a[mt][3],
                       as_ + (uint32_t)(r * LDH + k + a_k) * 2);
            }
            uint32_t b[4][2];
            #pragma unroll
            for (int q = 0; q < 2; q++) {
                int r = wn * 32 + q * 16 + b_r;
                uint32_t t0, t1, t2, t3;
                ldm_x4(t0, t1, t2, t3, bs_ + (uint32_t)(r * LDH + k + b_k) * 2);
                b[2 * q][0] = t0;  b[2 * q][1] = t1;
                b[2 * q + 1][0] = t2;  b[2 * q + 1][1] = t3;
            }
            #pragma unroll
            for (int mt = 0; mt < 2; mt++)
                #pragma unroll
                for (int nt = 0; nt < 4; nt++)
                    mma_f16(acc[mt][nt][0], acc[mt][nt][1],
                            acc[mt][nt][2], acc[mt][nt][3],
                            a[mt][0], a[mt][1], a[mt][2], a[mt][3],
                            b[nt][0], b[nt][1]);
        }
        __syncthreads();
    }

    #pragma unroll
    for (int mt = 0; mt < 2; mt++) {
        int gr0 = m0 + wm * 32 + mt * 16 + row;
        #pragma unroll
        for (int nt = 0; nt < 4; nt++) {
            int gc = wn * 32 + nt * 8 + qc * 2;
            float2 v0 = make_float2(acc[mt][nt][0], acc[mt][nt][1]);
            float2 v1 = make_float2(acc[mt][nt][2], acc[mt][nt][3]);
            *(float2*)(dbc + (size_t)gr0 * NDBC + gc)       = v0;
            *(float2*)(dbc + (size_t)(gr0 + 8) * NDBC + gc) = v1;
            if (gc < DTRANK) {
                ((__half2*)(dtlo + (size_t)gr0 * DTRANK))[gc >> 1] =
                    __floats2half2_rn(v0.x, v0.y);
                ((__half2*)(dtlo + (size_t)(gr0 + 8) * DTRANK))[gc >> 1] =
                    __floats2half2_rn(v1.x, v1.y);
            }
        }
    }
}

// ---------------------------------------------------------------------------
// multi-segment transpose fp32[K,N] -> fp16[N,K]
// ---------------------------------------------------------------------------
__global__ void __launch_bounds__(256) transpose_m4(
    const float* in0, __half* out0, int K0, int N0, int gx0, int c1,
    const float* in1, __half* out1, int K1, int N1, int gx1, int c2,
    const float* in2, __half* out2, int K2, int N2, int gx2, int c3,
    const float* in3, __half* out3, int K3, int N3, int gx3)
{
    int b = blockIdx.x;
    const float* in; __half* out; int K, N, gx, local;
    if (b < c1)      { in = in0; out = out0; K = K0; N = N0; gx = gx0; local = b; }
    else if (b < c2) { in = in1; out = out1; K = K1; N = N1; gx = gx1; local = b - c1; }
    else if (b < c3) { in = in2; out = out2; K = K2; N = N2; gx = gx2; local = b - c2; }
    else             { in = in3; out = out3; K = K3; N = N3; gx = gx3; local = b - c3; }
    int n0 = (local % gx) * 32;
    int k0 = (local / gx) * 32;

    __shared__ float t[32][33];
    int x = threadIdx.x & 31, y = threadIdx.x >> 5;
    #pragma unroll
    for (int i = 0; i < 4; i++)
        t[y + 8 * i][x] = in[(size_t)(k0 + y + 8 * i) * N + n0 + x];
    __syncthreads();
    #pragma unroll
    for (int i = 0; i < 4; i++)
        out[(size_t)(n0 + y + 8 * i) * K + k0 + x] = __float2half_rn(t[x][y + 8 * i]);
}

// ---------------------------------------------------------------------------
__global__ void __launch_bounds__(256) ln_kernel(
    const float* __restrict__ x, const float* __restrict__ g,
    const float* __restrict__ b, __half* __restrict__ out)
{
    int t = blockIdx.x, tid = threadIdx.x;
    float4 v = ((const float4*)(x + (size_t)t * DMODEL))[tid];
    float s  = v.x + v.y + v.z + v.w;
    float ss = fmaf(v.x, v.x, fmaf(v.y, v.y, fmaf(v.z, v.z, v.w * v.w)));
    #pragma unroll
    for (int o = 16; o > 0; o >>= 1) {
        s  += __shfl_down_sync(0xffffffffu, s, o);
        ss += __shfl_down_sync(0xffffffffu, ss, o);
    }
    __shared__ float rs_[8], rss_[8];
    __shared__ float smu, srs;
    int warp = tid >> 5, lane = tid & 31;
    if (lane == 0) { rs_[warp] = s; rss_[warp] = ss; }
    __syncthreads();
    if (tid == 0) {
        float S = 0.f, SS = 0.f;
        #pragma unroll
        for (int w = 0; w < 8; w++) { S += rs_[w]; SS += rss_[w]; }
        float mu = S * (1.f / DMODEL);
        smu = mu;
        srs = rsqrtf(SS * (1.f / DMODEL) - mu * mu + 1e-5f);
    }
    __syncthreads();
    float mu = smu, rs = srs;
    float4 gv = ((const float4*)g)[tid];
    float4 bv = ((const float4*)b)[tid];
    __half2 p0 = __floats2half2_rn((v.x - mu) * rs * gv.x + bv.x,
                                   (v.y - mu) * rs * gv.y + bv.y);
    __half2 p1 = __floats2half2_rn((v.z - mu) * rs * gv.z + bv.z,
                                   (v.w - mu) * rs * gv.w + bv.w);
    __half2* orow = (__half2*)(out + (size_t)t * DMODEL);
    orow[2 * tid]     = p0;
    orow[2 * tid + 1] = p1;
}

// ---------------------------------------------------------------------------
// conv + silu: fp32 out (scan) + fp16 out (wx GEMM)
// ---------------------------------------------------------------------------
__global__ void __launch_bounds__(256) conv_silu_kernel(
    const float* __restrict__ xz, const float* __restrict__ w,
    const float* __restrict__ cb, float* __restrict__ out,
    __half* __restrict__ outh)
{
    int idx = blockIdx.x * 256 + threadIdx.x;
    int d = idx & (DINNER - 1);
    int t = idx >> 11;
    int l = t & (LSEQ - 1);
    float w0 = w[d * 4 + 0], w1 = w[d * 4 + 1], w2 = w[d * 4 + 2], w3 = w[d * 4 + 3];
    float s = cb[d];
    const float* base = xz + (size_t)t * (2 * DINNER) + d;
    if (l >= 3) s = fmaf(w0, base[-3 * (ptrdiff_t)(2 * DINNER)], s);
    if (l >= 2) s = fmaf(w1, base[-2 * (ptrdiff_t)(2 * DINNER)], s);
    if (l >= 1) s = fmaf(w2, base[-1 * (ptrdiff_t)(2 * DINNER)], s);
    s = fmaf(w3, base[0], s);
    float r = s / (1.f + expf(-s));
    out[idx]  = r;
    outh[idx] = __float2half_rn(r);
}

// ---------------------------------------------------------------------------
// selective scan, 8-deep prefetch ring; all hot streams fp32
// ---------------------------------------------------------------------------
#define PFD 8
__global__ void __launch_bounds__(256) scan_kernel(
    const float* __restrict__ dt, const float* __restrict__ xc,
    const float* __restrict__ dbc, const float* __restrict__ xz,
    const float* __restrict__ a_log, const float* __restrict__ d_skip,
    __half* __restrict__ y)
{
    int warp = threadIdx.x >> 5;
    int lane = threadIdx.x & 31;
    int half_ = lane >> 4;
    int n    = lane & 15;
    int gchan = blockIdx.x * 16 + warp * 2 + half_;
    int b = gchan >> 11;
    int d = gchan & (DINNER - 1);
    float Acoef = -expf(a_log[d * DSTATE + n]);
    float Dsk   = d_skip[d];
    float s = 0.f;
    int t0 = b * LSEQ;

    float dtb[PFD], xb[PFD], Bb[PFD], Cb[PFD], zb[PFD];
    #pragma unroll
    for (int i = 0; i < PFD; i++) {
        int t = t0 + i;
        dtb[i] = dt [(size_t)t * DINNER + d];
        xb [i] = xc [(size_t)t * DINNER + d];
        Bb [i] = dbc[(size_t)t * NDBC + 64 + n];
        Cb [i] = dbc[(size_t)t * NDBC + 80 + n];
        zb [i] = (n == 0) ? xz[(size_t)t * (2 * DINNER) + DINNER + d] : 0.f;
    }

    #pragma unroll 8
    for (int l = 0; l < LSEQ; l++) {
        int bi = l & (PFD - 1);
        float dt_c = dtb[bi], x_c = xb[bi], B_c = Bb[bi], C_c = Cb[bi], z_c = zb[bi];
        int lp = l + PFD;
        if (lp < LSEQ) {
            int t2 = t0 + lp;
            dtb[bi] = dt [(size_t)t2 * DINNER + d];
            xb [bi] = xc [(size_t)t2 * DINNER + d];
            Bb [bi] = dbc[(size_t)t2 * NDBC + 64 + n];
            Cb [bi] = dbc[(size_t)t2 * NDBC + 80 + n];
            if (n == 0) zb[bi] = xz[(size_t)t2 * (2 * DINNER) + DINNER + d];
        }
        float dA = __expf(dt_c * Acoef);
        s = fmaf(s, dA, dt_c * x_c * B_c);
        float part = s * C_c;
        part += __shfl_down_sync(0xffffffffu, part, 8, 16);
        part += __shfl_down_sync(0xffffffffu, part, 4, 16);
        part += __shfl_down_sync(0xffffffffu, part, 2, 16);
        part += __shfl_down_sync(0xffffffffu, part, 1, 16);
        if (n == 0) {
            float yv = part + Dsk * x_c;
            yv = yv * (z_c / (1.f + __expf(-z_c)));
            y[(size_t)(t0 + l) * DINNER + d] = __float2half_rn(yv);
        }
    }
}

// ---------------------------------------------------------------------------
extern "C" void kernel_launch(void* const* d_in, const int* in_sizes, int n_in,
                              void* d_out, int out_size)
{
    const float* x      = (const float*)d_in[0];
    const float* ln1_g  = (const float*)d_in[1];
    const float* ln1_b  = (const float*)d_in[2];
    const float* w_in   = (const float*)d_in[3];
    const float* conv_w = (const float*)d_in[4];
    const float* conv_b = (const float*)d_in[5];
    const float* w_x    = (const float*)d_in[6];
    const float* w_dt   = (const float*)d_in[7];
    const float* b_dt   = (const float*)d_in[8];
    const float* a_log  = (const float*)d_in[9];
    const float* d_skip = (const float*)d_in[10];
    const float* w_out  = (const float*)d_in[11];
    const float* ln2_g  = (const float*)d_in[12];
    const float* ln2_b  = (const float*)d_in[13];
    const float* w_ff1  = (const float*)d_in[14];
    const float* b_ff1  = (const float*)d_in[15];
    const float* w_ff2  = (const float*)d_in[16];
    const float* b_ff2  = (const float*)d_in[17];
    float* out = (float*)d_out;

    __half *h, *xch, *dtlo, *y, *h2, *pa, *ffa;
    __half *wtin, *wtout, *wtff1, *wtff2, *wxt, *wdtt;
    float *xz, *xc, *dbc, *dtb, *out1;
    cudaGetSymbolAddress((void**)&h,     g_h);
    cudaGetSymbolAddress((void**)&xz,    g_xz);
    cudaGetSymbolAddress((void**)&xc,    g_xc);
    cudaGetSymbolAddress((void**)&xch,   g_xch);
    cudaGetSymbolAddress((void**)&dbc,   g_dbc);
    cudaGetSymbolAddress((void**)&dtlo,  g_dtlo);
    cudaGetSymbolAddress((void**)&dtb,   g_dt);
    cudaGetSymbolAddress((void**)&y,     g_y);
    cudaGetSymbolAddress((void**)&out1,  g_out1);
    cudaGetSymbolAddress((void**)&h2,    g_h2);
    cudaGetSymbolAddress((void**)&pa,    g_pa);
    cudaGetSymbolAddress((void**)&ffa,   g_ffa);
    cudaGetSymbolAddress((void**)&wtin,  g_wtin);
    cudaGetSymbolAddress((void**)&wtout, g_wtout);
    cudaGetSymbolAddress((void**)&wtff1, g_wtff1);
    cudaGetSymbolAddress((void**)&wtff2, g_wtff2);
    cudaGetSymbolAddress((void**)&wxt,   g_wxt);
    cudaGetSymbolAddress((void**)&wdtt,  g_wdtt);

    cudaFuncSetAttribute(mh_gemm<0>, cudaFuncAttributeMaxDynamicSharedMemorySize, MH_SMEM);
    cudaFuncSetAttribute(mh_gemm<2>, cudaFuncAttributeMaxDynamicSharedMemorySize, MH_SMEM);
    cudaFuncSetAttribute(mh_gemm<3>, cudaFuncAttributeMaxDynamicSharedMemorySize, MH_SMEM);
    cudaFuncSetAttribute(mh_gemm<5>, cudaFuncAttributeMaxDynamicSharedMemorySize, MH_SMEM);
    cudaFuncSetAttribute(mha_gemm,   cudaFuncAttributeMaxDynamicSharedMemorySize, MH_SMEM);
    cudaFuncSetAttribute(mhg_gemm,   cudaFuncAttributeMaxDynamicSharedMemorySize, MH_SMEM);
    cudaFuncSetAttribute(wx_tc,      cudaFuncAttributeMaxDynamicSharedMemorySize, WX_SMEM);

    // 1. transpose group A: w_in | w_out | w_x | w_dt
    transpose_m4<<<6464, 256>>>(
        w_in,  wtin,  1024, 4096, 128, 4096,
        w_out, wtout, 2048, 1024, 32,  6144,
        w_x,   wxt,   2048, 96,   3,   6336,
        w_dt,  wdtt,  64,   2048, 64);
    // 2. ln1 (fp16 out)
    ln_kernel<<<TOKENS, 256>>>(x, ln1_g, ln1_b, h);
    // 3. transpose group B: w_ff1 | w_ff2
    transpose_m4<<<12288, 256>>>(
        w_ff1, wtff1, 1024, 8192, 256, 8192,
        w_ff2, wtff2, 4096, 1024, 32,  12288,
        w_ff2, wtff2, 4096, 1024, 32,  12288,
        w_ff2, wtff2, 4096, 1024, 32);
    // 4. xz = h @ w_in  [ncu-sampled control]
    mh_gemm<0><<<dim3(4096 / BN, TOKENS / BM), 256, MH_SMEM>>>(
        h, wtin, xz, nullptr, nullptr, 1024, 4096);
    // 5. conv + silu
    conv_silu_kernel<<<(TOKENS * DINNER) / 256, 256>>>(xz, conv_w, conv_b, xc, xch);
    // 6. dbc = xch @ w_x^T + fp16 dt_lo copy
    wx_tc<<<dim3(1, TOKENS / 64), 256, WX_SMEM>>>(xch, wxt, dbc, dtlo);
    // 7. dt = softplus(dt_lo @ w_dt + b_dt)
    mh_gemm<5><<<dim3(DINNER / BN, TOKENS / BM), 256, MH_SMEM>>>(
        dtlo, wdtt, dtb, b_dt, nullptr, 64, DINNER);
    // 8. scan
    scan_kernel<<<(2 * DINNER) / 16, 256>>>(dtb, xc, dbc, xz, a_log, d_skip, y);
    // 9. out1 = x + y @ w_out
    mh_gemm<2><<<dim3(DMODEL / BN, TOKENS / BM), 256, MH_SMEM>>>(
        y, wtout, out1, nullptr, x, 2048, DMODEL);
    // 10. ln2
    ln_kernel<<<TOKENS, 256>>>(out1, ln2_g, ln2_b, h2);
    // 11a. ff1 a-half: pa = h2 @ Wa + ba  (fp16)
    mha_gemm<<<dim3(FFIN / BN, TOKENS / BM), 256, MH_SMEM>>>(
        h2, wtff1, pa, b_ff1, 1024, FFIN);
    // 11b. ff1 g-half + geglu: ffa = pa * gelu(h2 @ Wg + bg)
    mhg_gemm<<<dim3(FFIN / BN, TOKENS / BM), 256, MH_SMEM>>>(
        h2, wtff1 + (size_t)4096 * 1024, ffa, b_ff1 + FFIN, pa, 1024, FFIN);
    // 12. out = out1 + ffa @ w_ff2 + b_ff2
    mh_gemm<3><<<dim3(DMODEL / BN, TOKENS / BM), 256, MH_SMEM>>>(
        ffa, wtff2, out, b_ff2, out1, FFIN, DMODEL);
}

// round 14
// speedup vs baseline: 1.0339x; 1.0339x over previous
#include <cuda_runtime.h>
#include <cuda_fp16.h>
#include <math.h>
#include <stdint.h>

#define TOKENS   4096
#define DMODEL   1024
#define DINNER   2048
#define DSTATE   16
#define DTRANK   64
#define FFIN     4096
#define LSEQ     2048
#define NDBC     128

// ---------------- scratch ----------------
__device__ __align__(128) __half g_h    [TOKENS * DMODEL];
__device__ __align__(128) float  g_xz   [TOKENS * 2 * DINNER];
__device__ __align__(128) float  g_xc   [TOKENS * DINNER];
__device__ __align__(128) __half g_xch  [TOKENS * DINNER];
__device__ __align__(128) float  g_dbc  [TOKENS * NDBC];   // cols 64..95: B0,C0,B1,C1,...
__device__ __align__(128) __half g_dtlo [TOKENS * DTRANK];
__device__ __align__(128) float  g_dt   [TOKENS * DINNER];
__device__ __align__(128) __half g_y    [TOKENS * DINNER];
__device__ __align__(128) float  g_out1 [TOKENS * DMODEL];
__device__ __align__(128) __half g_h2   [TOKENS * DMODEL];
__device__ __align__(128) __half g_ffa  [TOKENS * FFIN];
__device__ __align__(128) __half g_wtin [4096 * 1024];
__device__ __align__(128) __half g_wtout[1024 * 2048];
__device__ __align__(128) __half g_wtff1[8192 * 1024];
__device__ __align__(128) __half g_wtff2[1024 * 4096];
__device__ __align__(128) __half g_wxt  [128 * 2048];
__device__ __align__(128) __half g_wdtt [2048 * 64];

// ---------------- helpers ----------------
__device__ __forceinline__ float softplus_f(float x) {
    return (x > 20.f) ? x : log1pf(expf(x));
}
__device__ __forceinline__ float tanh_ap(float x) {
    float r;
    asm("tanh.approx.f32 %0, %1;" : "=f"(r) : "f"(x));
    return r;
}
__device__ __forceinline__ float gelu_t(float g) {
    float u = 0.7978845608028654f * fmaf(0.044715f * g * g, g, g);
    return 0.5f * g * (1.f + tanh_ap(u));
}
__device__ __forceinline__ uint32_t smem_u32(const void* p) {
    uint32_t a;
    asm("{ .reg .u64 t; cvta.to.shared.u64 t, %1; cvt.u32.u64 %0, t; }" : "=r"(a) : "l"(p));
    return a;
}
__device__ __forceinline__ void cp16(uint32_t dst, const void* src) {
    asm volatile("cp.async.cg.shared.global [%0], [%1], 16;" :: "r"(dst), "l"(src));
}
#define CP_COMMIT() asm volatile("cp.async.commit_group;" ::: "memory")
#define CP_WAIT0()  asm volatile("cp.async.wait_group 0;" ::: "memory")
#define CP_WAIT1()  asm volatile("cp.async.wait_group 1;" ::: "memory")

__device__ __forceinline__ void ldm_x4(uint32_t& r0, uint32_t& r1,
                                       uint32_t& r2, uint32_t& r3, uint32_t addr)
{
    asm volatile("ldmatrix.sync.aligned.m8n8.x4.shared.b16 {%0,%1,%2,%3}, [%4];"
                 : "=r"(r0), "=r"(r1), "=r"(r2), "=r"(r3) : "r"(addr));
}
__device__ __forceinline__ void mma_f16(
    float& c0, float& c1, float& c2, float& c3,
    uint32_t a0, uint32_t a1, uint32_t a2, uint32_t a3,
    uint32_t b0, uint32_t b1)
{
    asm volatile(
        "mma.sync.aligned.m16n8k16.row.col.f32.f16.f16.f32 "
        "{%0,%1,%2,%3}, {%4,%5,%6,%7}, {%8,%9}, {%0,%1,%2,%3};"
        : "+f"(c0), "+f"(c1), "+f"(c2), "+f"(c3)
        : "r"(a0), "r"(a1), "r"(a2), "r"(a3), "r"(b0), "r"(b1));
}

// ---------------------------------------------------------------------------
// fp16 tensor GEMM: C[M,N] = A[M,K] @ Bw[N,K]^T, 128x128 tile, 3-stage pipe.
// MODE bits: 1 = +bias[n], 2 = +res[m,n], 4 = softplus
// ---------------------------------------------------------------------------
#define BM 128
#define BN 128
#define BKH 64
#define LDH 72
#define HSTG ((BM + BN) * LDH)
#define MH_SMEM (3 * HSTG * 2)

__device__ __forceinline__ void mh_load(
    const __half* __restrict__ A, const __half* __restrict__ Bw, int K,
    int m0, int n0, uint32_t sbyte, int stage, int chunk, int tid)
{
    uint32_t ab = sbyte + (uint32_t)stage * (HSTG * 2);
    uint32_t bb = ab + BM * LDH * 2;
    const __half* Ap = A  + (size_t)m0 * K + chunk * BKH;
    const __half* Bp = Bw + (size_t)n0 * K + chunk * BKH;
    #pragma unroll
    for (int p = 0; p < 4; p++) {
        int idx = tid + (p << 8);
        int r = idx >> 3, c = idx & 7;
        cp16(ab + (uint32_t)(r * LDH + c * 8) * 2, Ap + (size_t)r * K + c * 8);
    }
    #pragma unroll
    for (int p = 0; p < 4; p++) {
        int idx = tid + (p << 8);
        int r = idx >> 3, c = idx & 7;
        cp16(bb + (uint32_t)(r * LDH + c * 8) * 2, Bp + (size_t)r * K + c * 8);
    }
}

template <int MODE>
__global__ void __launch_bounds__(256, 2) mh_gemm(
    const __half* __restrict__ A, const __half* __restrict__ Bw,
    float* __restrict__ C, const float* __restrict__ bias,
    const float* __restrict__ res, int K, int N)
{
    extern __shared__ char smraw[];
    const uint32_t sbyte = smem_u32(smraw);
    const int tid  = threadIdx.x;
    const int lane = tid & 31;
    const int wid  = tid >> 5;
    const int wm   = wid >> 1;
    const int wn   = wid & 1;
    const int row  = lane >> 2;
    const int qc   = lane & 3;
    const int m0 = blockIdx.y * BM;
    const int n0 = blockIdx.x * BN;

    const int a_r  = ((lane >> 3) & 1) * 8 + (lane & 7);
    const int a_k  = (lane >> 4) * 8;
    const int b_r  = (lane >> 4) * 8 + (lane & 7);
    const int b_k  = ((lane >> 3) & 1) * 8;

    float acc[2][8][4];
    #pragma unroll
    for (int i = 0; i < 2; i++)
        #pragma unroll
        for (int j = 0; j < 8; j++)
            #pragma unroll
            for (int q = 0; q < 4; q++) acc[i][j][q] = 0.f;

    const int nc = K / BKH;
    mh_load(A, Bw, K, m0, n0, sbyte, 0, 0, tid);
    CP_COMMIT();
    if (1 < nc) mh_load(A, Bw, K, m0, n0, sbyte, 1, 1, tid);
    CP_COMMIT();

    int stage = 0;
    for (int ks = 0; ks < nc; ks++) {
        if (ks + 1 < nc) { CP_WAIT1(); } else { CP_WAIT0(); }
        __syncthreads();
        int ldst = stage + 2; if (ldst >= 3) ldst -= 3;
        if (ks + 2 < nc)
            mh_load(A, Bw, K, m0, n0, sbyte, ldst, ks + 2, tid);
        CP_COMMIT();

        uint32_t as_ = sbyte + (uint32_t)stage * (HSTG * 2);
        uint32_t bs_ = as_ + BM * LDH * 2;
        #pragma unroll
        for (int kk = 0; kk < 4; kk++) {
            int k = kk * 16;
            uint32_t a[2][4];
            #pragma unroll
            for (int mt = 0; mt < 2; mt++) {
                int r = wm * 32 + mt * 16 + a_r;
                ldm_x4(a[mt][0], a[mt][1], a[mt][2], a[mt][3],
                       as_ + (uint32_t)(r * LDH + k + a_k) * 2);
            }
            uint32_t b[8][2];
            #pragma unroll
            for (int q = 0; q < 4; q++) {
                int r = wn * 64 + q * 16 + b_r;
                uint32_t t0, t1, t2, t3;
                ldm_x4(t0, t1, t2, t3,
                       bs_ + (uint32_t)(r * LDH + k + b_k) * 2);
                b[2 * q][0] = t0;  b[2 * q][1] = t1;
                b[2 * q + 1][0] = t2;  b[2 * q + 1][1] = t3;
            }
            #pragma unroll
            for (int mt = 0; mt < 2; mt++)
                #pragma unroll
                for (int nt = 0; nt < 8; nt++)
                    mma_f16(acc[mt][nt][0], acc[mt][nt][1],
                            acc[mt][nt][2], acc[mt][nt][3],
                            a[mt][0], a[mt][1], a[mt][2], a[mt][3],
                            b[nt][0], b[nt][1]);
        }
        stage++; if (stage >= 3) stage -= 3;
    }

    #pragma unroll
    for (int mt = 0; mt < 2; mt++) {
        int gr0 = m0 + wm * 32 + mt * 16 + row;
        #pragma unroll
        for (int nt = 0; nt < 8; nt++) {
            int gc = n0 + wn * 64 + nt * 8 + qc * 2;
            float2 v0 = make_float2(acc[mt][nt][0], acc[mt][nt][1]);
            float2 v1 = make_float2(acc[mt][nt][2], acc[mt][nt][3]);
            if (MODE & 1) {
                float2 bb = *(const float2*)(bias + gc);
                v0.x += bb.x; v0.y += bb.y;
                v1.x += bb.x; v1.y += bb.y;
            }
            if (MODE & 4) {
                v0.x = softplus_f(v0.x); v0.y = softplus_f(v0.y);
                v1.x = softplus_f(v1.x); v1.y = softplus_f(v1.y);
            }
            if (MODE & 2) {
                float2 r0 = *(const float2*)(res + (size_t)gr0 * N + gc);
                float2 r1 = *(const float2*)(res + (size_t)(gr0 + 8) * N + gc);
                v0.x += r0.x; v0.y += r0.y;
                v1.x += r1.x; v1.y += r1.y;
            }
            *(float2*)(C + (size_t)gr0 * N + gc)       = v0;
            *(float2*)(C + (size_t)(gr0 + 8) * N + gc) = v1;
        }
    }
}

// ---------------------------------------------------------------------------
// wx tensor GEMM: dbc[M,128] = xch[M,2048] @ wxt[128,2048]^T
// epilogue writes B/C INTERLEAVED: col 64+2n = B_n, col 64+2n+1 = C_n
// ---------------------------------------------------------------------------
#define WXSTG ((64 + 128) * LDH)
#define WX_SMEM (2 * WXSTG * 2)

__device__ __forceinline__ void wx_load(
    const __half* __restrict__ A, const __half* __restrict__ Bw,
    int m0, uint32_t sbyte, int stage, int chunk, int tid)
{
    uint32_t ab = sbyte + (uint32_t)stage * (WXSTG * 2);
    uint32_t bb = ab + 64 * LDH * 2;
    const __half* Ap = A  + (size_t)m0 * DINNER + chunk * BKH;
    const __half* Bp = Bw + chunk * BKH;
    #pragma unroll
    for (int p = 0; p < 2; p++) {
        int idx = tid + (p << 8);
        int r = idx >> 3, c = idx & 7;
        cp16(ab + (uint32_t)(r * LDH + c * 8) * 2, Ap + (size_t)r * DINNER + c * 8);
    }
    #pragma unroll
    for (int p = 0; p < 4; p++) {
        int idx = tid + (p << 8);
        int r = idx >> 3, c = idx & 7;
        cp16(bb + (uint32_t)(r * LDH + c * 8) * 2, Bp + (size_t)r * DINNER + c * 8);
    }
}

__device__ __forceinline__ int dbc_col(int c) {
    // old col -> interleaved col
    if (c < 64) return c;
    if (c < 80) return 64 + 2 * (c - 64);       // B_n
    return 64 + 2 * (c - 80) + 1;               // C_n
}

__global__ void __launch_bounds__(256, 2) wx_tc(
    const __half* __restrict__ A, const __half* __restrict__ Bw,
    float* __restrict__ dbc, __half* __restrict__ dtlo)
{
    extern __shared__ char smraw[];
    const uint32_t sbyte = smem_u32(smraw);
    const int tid  = threadIdx.x;
    const int lane = tid & 31;
    const int wid  = tid >> 5;
    const int wm   = wid >> 2;
    const int wn   = wid & 3;
    const int row  = lane >> 2;
    const int qc   = lane & 3;
    const int m0 = blockIdx.y * 64;

    const int a_r  = ((lane >> 3) & 1) * 8 + (lane & 7);
    const int a_k  = (lane >> 4) * 8;
    const int b_r  = (lane >> 4) * 8 + (lane & 7);
    const int b_k  = ((lane >> 3) & 1) * 8;

    float acc[2][4][4];
    #pragma unroll
    for (int i = 0; i < 2; i++)
        #pragma unroll
        for (int j = 0; j < 4; j++)
            #pragma unroll
            for (int q = 0; q < 4; q++) acc[i][j][q] = 0.f;

    const int nc = DINNER / BKH;
    wx_load(A, Bw, m0, sbyte, 0, 0, tid);
    CP_COMMIT();

    for (int ks = 0; ks < nc; ks++) {
        if (ks + 1 < nc) {
            wx_load(A, Bw, m0, sbyte, (ks + 1) & 1, ks + 1, tid);
            CP_COMMIT();
            CP_WAIT1();
        } else {
            CP_WAIT0();
        }
        __syncthreads();

        uint32_t as_ = sbyte + (uint32_t)(ks & 1) * (WXSTG * 2);
        uint32_t bs_ = as_ + 64 * LDH * 2;
        #pragma unroll
        for (int kk = 0; kk < 4; kk++) {
            int k = kk * 16;
            uint32_t a[2][4];
            #pragma unroll
            for (int mt = 0; mt < 2; mt++) {
                int r = wm * 32 + mt * 16 + a_r;
                ldm_x4(a[mt][0], a[mt][1], a[mt][2], a[mt][3],
                       as_ + (uint32_t)(r * LDH + k + a_k) * 2);
            }
            uint32_t b[4][2];
            #pragma unroll
            for (int q = 0; q < 2; q++) {
                int r = wn * 32 + q * 16 + b_r;
                uint32_t t0, t1, t2, t3;
                ldm_x4(t0, t1, t2, t3, bs_ + (uint32_t)(r * LDH + k + b_k) * 2);
                b[2 * q][0] = t0;  b[2 * q][1] = t1;
                b[2 * q + 1][0] = t2;  b[2 * q + 1][1] = t3;
            }
            #pragma unroll
            for (int mt = 0; mt < 2; mt++)
                #pragma unroll
                for (int nt = 0; nt < 4; nt++)
                    mma_f16(acc[mt][nt][0], acc[mt][nt][1],
                            acc[mt][nt][2], acc[mt][nt][3],
                            a[mt][0], a[mt][1], a[mt][2], a[mt][3],
                            b[nt][0], b[nt][1]);
        }
        __syncthreads();
    }

    #pragma unroll
    for (int mt = 0; mt < 2; mt++) {
        int gr0 = m0 + wm * 32 + mt * 16 + row;
        #pragma unroll
        for (int nt = 0; nt < 4; nt++) {
            int gc = wn * 32 + nt * 8 + qc * 2;
            float2 v0 = make_float2(acc[mt][nt][0], acc[mt][nt][1]);
            float2 v1 = make_float2(acc[mt][nt][2], acc[mt][nt][3]);
            // interleaved scatter (scalar stores; wx is tiny)
            dbc[(size_t)gr0 * NDBC + dbc_col(gc)]           = v0.x;
            dbc[(size_t)gr0 * NDBC + dbc_col(gc + 1)]       = v0.y;
            dbc[(size_t)(gr0 + 8) * NDBC + dbc_col(gc)]     = v1.x;
            dbc[(size_t)(gr0 + 8) * NDBC + dbc_col(gc + 1)] = v1.y;
            if (gc < DTRANK) {
                ((__half2*)(dtlo + (size_t)gr0 * DTRANK))[gc >> 1] =
                    __floats2half2_rn(v0.x, v0.y);
                ((__half2*)(dtlo + (size_t)(gr0 + 8) * DTRANK))[gc >> 1] =
                    __floats2half2_rn(v1.x, v1.y);
            }
        }
    }
}

// ---------------------------------------------------------------------------
// Fused ff1 + geglu, 128x64 tile, 3-stage pipeline
// ---------------------------------------------------------------------------
#define FG_SMEM MH_SMEM

__device__ __forceinline__ void fg_load(
    const __half* __restrict__ A, const __half* __restrict__ Bw, int K,
    int m0, int n0, uint32_t sbyte, int stage, int chunk, int tid)
{
    uint32_t ab  = sbyte + (uint32_t)stage * (HSTG * 2);
    uint32_t bab = ab  + BM * LDH * 2;
    uint32_t bgb = bab + 64 * LDH * 2;
    const __half* Ap  = A  + (size_t)m0 * K + chunk * BKH;
    const __half* Bap = Bw + (size_t)n0 * K + chunk * BKH;
    const __half* Bgp = Bw + (size_t)(4096 + n0) * K + chunk * BKH;
    #pragma unroll
    for (int p = 0; p < 4; p++) {
        int idx = tid + (p << 8);
        int r = idx >> 3, c = idx & 7;
        cp16(ab + (uint32_t)(r * LDH + c * 8) * 2, Ap + (size_t)r * K + c * 8);
    }
    #pragma unroll
    for (int p = 0; p < 2; p++) {
        int idx = tid + (p << 8);
        int r = idx >> 3, c = idx & 7;
        cp16(bab + (uint32_t)(r * LDH + c * 8) * 2, Bap + (size_t)r * K + c * 8);
    }
    #pragma unroll
    for (int p = 0; p < 2; p++) {
        int idx = tid + (p << 8);
        int r = idx >> 3, c = idx & 7;
        cp16(bgb + (uint32_t)(r * LDH + c * 8) * 2, Bgp + (size_t)r * K + c * 8);
    }
}

__global__ void __launch_bounds__(256, 2) fg_gemm(
    const __half* __restrict__ A, const __half* __restrict__ Bw,
    __half* __restrict__ out, const float* __restrict__ bias, int K)
{
    extern __shared__ char smraw[];
    const uint32_t sbyte = smem_u32(smraw);
    const int tid  = threadIdx.x;
    const int lane = tid & 31;
    const int wid  = tid >> 5;
    const int wm   = wid >> 1;
    const int wn   = wid & 1;
    const int row  = lane >> 2;
    const int qc   = lane & 3;
    const int m0 = blockIdx.y * BM;
    const int n0 = blockIdx.x * 64;

    const int a_r  = ((lane >> 3) & 1) * 8 + (lane & 7);
    const int a_k  = (lane >> 4) * 8;
    const int b_r  = (lane >> 4) * 8 + (lane & 7);
    const int b_k  = ((lane >> 3) & 1) * 8;

    float acca[2][4][4], accg[2][4][4];
    #pragma unroll
    for (int i = 0; i < 2; i++)
        #pragma unroll
        for (int j = 0; j < 4; j++)
            #pragma unroll
            for (int q = 0; q < 4; q++) { acca[i][j][q] = 0.f; accg[i][j][q] = 0.f; }

    const int nc = K / BKH;
    fg_load(A, Bw, K, m0, n0, sbyte, 0, 0, tid);
    CP_COMMIT();
    if (1 < nc) fg_load(A, Bw, K, m0, n0, sbyte, 1, 1, tid);
    CP_COMMIT();

    int stage = 0;
    for (int ks = 0; ks < nc; ks++) {
        if (ks + 1 < nc) { CP_WAIT1(); } else { CP_WAIT0(); }
        __syncthreads();
        int ldst = stage + 2; if (ldst >= 3) ldst -= 3;
        if (ks + 2 < nc)
            fg_load(A, Bw, K, m0, n0, sbyte, ldst, ks + 2, tid);
        CP_COMMIT();

        uint32_t as_ = sbyte + (uint32_t)stage * (HSTG * 2);
        uint32_t ba_ = as_ + BM * LDH * 2;
        uint32_t bg_ = ba_ + 64 * LDH * 2;
        #pragma unroll
        for (int kk = 0; kk < 4; kk++) {
            int k = kk * 16;
            uint32_t a[2][4];
            #pragma unroll
            for (int mt = 0; mt < 2; mt++) {
                int r = wm * 32 + mt * 16 + a_r;
                ldm_x4(a[mt][0], a[mt][1], a[mt][2], a[mt][3],
                       as_ + (uint32_t)(r * LDH + k + a_k) * 2);
            }
            uint32_t ba[4][2], bg[4][2];
            #pragma unroll
            for (int q = 0; q < 2; q++) {
                int r = wn * 32 + q * 16 + b_r;
                uint32_t t0, t1, t2, t3;
                ldm_x4(t0, t1, t2, t3, ba_ + (uint32_t)(r * LDH + k + b_k) * 2);
                ba[2 * q][0] = t0;  ba[2 * q][1] = t1;
                ba[2 * q + 1][0] = t2;  ba[2 * q + 1][1] = t3;
                ldm_x4(t0, t1, t2, t3, bg_ + (uint32_t)(r * LDH + k + b_k) * 2);
                bg[2 * q][0] = t0;  bg[2 * q][1] = t1;
                bg[2 * q + 1][0] = t2;  bg[2 * q + 1][1] = t3;
            }
            #pragma unroll
            for (int mt = 0; mt < 2; mt++)
                #pragma unroll
                for (int nt = 0; nt < 4; nt++) {
                    mma_f16(acca[mt][nt][0], acca[mt][nt][1],
                            acca[mt][nt][2], acca[mt][nt][3],
                            a[mt][0], a[mt][1], a[mt][2], a[mt][3],
                            ba[nt][0], ba[nt][1]);
                    mma_f16(accg[mt][nt][0], accg[mt][nt][1],
                            accg[mt][nt][2], accg[mt][nt][3],
                            a[mt][0], a[mt][1], a[mt][2], a[mt][3],
                            bg[nt][0], bg[nt][1]);
                }
        }
        stage++; if (stage >= 3) stage -= 3;
    }

    #pragma unroll
    for (int mt = 0; mt < 2; mt++) {
        int gr0 = m0 + wm * 32 + mt * 16 + row;
        #pragma unroll
        for (int nt = 0; nt < 4; nt++) {
            int gc = n0 + wn * 32 + nt * 8 + qc * 2;
            float2 bba = *(const float2*)(bias + gc);
            float2 bbg = *(const float2*)(bias + 4096 + gc);
            float a0 = acca[mt][nt][0] + bba.x, a1 = acca[mt][nt][1] + bba.y;
            float g0 = accg[mt][nt][0] + bbg.x, g1 = accg[mt][nt][1] + bbg.y;
            float a2 = acca[mt][nt][2] + bba.x, a3 = acca[mt][nt][3] + bba.y;
            float g2 = accg[mt][nt][2] + bbg.x, g3 = accg[mt][nt][3] + bbg.y;
            ((__half2*)(out + (size_t)gr0 * FFIN))[gc >> 1] =
                __floats2half2_rn(a0 * gelu_t(g0), a1 * gelu_t(g1));
            ((__half2*)(out + (size_t)(gr0 + 8) * FFIN))[gc >> 1] =
                __floats2half2_rn(a2 * gelu_t(g2), a3 * gelu_t(g3));
        }
    }
}

// ---------------------------------------------------------------------------
// 6-segment transpose fp32[K,N] -> fp16[N,K] (single launch for all weights)
// ---------------------------------------------------------------------------
__global__ void __launch_bounds__(256) transpose_m6(
    const float* in0, __half* out0, int K0, int N0, int gx0, int c1,
    const float* in1, __half* out1, int K1, int N1, int gx1, int c2,
    const float* in2, __half* out2, int K2, int N2, int gx2, int c3,
    const float* in3, __half* out3, int K3, int N3, int gx3, int c4,
    const float* in4, __half* out4, int K4, int N4, int gx4, int c5,
    const float* in5, __half* out5, int K5, int N5, int gx5)
{
    int b = blockIdx.x;
    const float* in; __half* out; int K, N, gx, local;
    if (b < c1)      { in = in0; out = out0; K = K0; N = N0; gx = gx0; local = b; }
    else if (b < c2) { in = in1; out = out1; K = K1; N = N1; gx = gx1; local = b - c1; }
    else if (b < c3) { in = in2; out = out2; K = K2; N = N2; gx = gx2; local = b - c2; }
    else if (b < c4) { in = in3; out = out3; K = K3; N = N3; gx = gx3; local = b - c3; }
    else if (b < c5) { in = in4; out = out4; K = K4; N = N4; gx = gx4; local = b - c4; }
    else             { in = in5; out = out5; K = K5; N = N5; gx = gx5; local = b - c5; }
    int n0 = (local % gx) * 32;
    int k0 = (local / gx) * 32;

    __shared__ float t[32][33];
    int x = threadIdx.x & 31, y = threadIdx.x >> 5;
    #pragma unroll
    for (int i = 0; i < 4; i++)
        t[y + 8 * i][x] = in[(size_t)(k0 + y + 8 * i) * N + n0 + x];
    __syncthreads();
    #pragma unroll
    for (int i = 0; i < 4; i++)
        out[(size_t)(n0 + y + 8 * i) * K + k0 + x] = __float2half_rn(t[x][y + 8 * i]);
}

// ---------------------------------------------------------------------------
__global__ void __launch_bounds__(256) ln_kernel(
    const float* __restrict__ x, const float* __restrict__ g,
    const float* __restrict__ b, __half* __restrict__ out)
{
    int t = blockIdx.x, tid = threadIdx.x;
    float4 v = ((const float4*)(x + (size_t)t * DMODEL))[tid];
    float s  = v.x + v.y + v.z + v.w;
    float ss = fmaf(v.x, v.x, fmaf(v.y, v.y, fmaf(v.z, v.z, v.w * v.w)));
    #pragma unroll
    for (int o = 16; o > 0; o >>= 1) {
        s  += __shfl_down_sync(0xffffffffu, s, o);
        ss += __shfl_down_sync(0xffffffffu, ss, o);
    }
    __shared__ float rs_[8], rss_[8];
    __shared__ float smu, srs;
    int warp = tid >> 5, lane = tid & 31;
    if (lane == 0) { rs_[warp] = s; rss_[warp] = ss; }
    __syncthreads();
    if (tid == 0) {
        float S = 0.f, SS = 0.f;
        #pragma unroll
        for (int w = 0; w < 8; w++) { S += rs_[w]; SS += rss_[w]; }
        float mu = S * (1.f / DMODEL);
        smu = mu;
        srs = rsqrtf(SS * (1.f / DMODEL) - mu * mu + 1e-5f);
    }
    __syncthreads();
    float mu = smu, rs = srs;
    float4 gv = ((const float4*)g)[tid];
    float4 bv = ((const float4*)b)[tid];
    __half2 p0 = __floats2half2_rn((v.x - mu) * rs * gv.x + bv.x,
                                   (v.y - mu) * rs * gv.y + bv.y);
    __half2 p1 = __floats2half2_rn((v.z - mu) * rs * gv.z + bv.z,
                                   (v.w - mu) * rs * gv.w + bv.w);
    __half2* orow = (__half2*)(out + (size_t)t * DMODEL);
    orow[2 * tid]     = p0;
    orow[2 * tid + 1] = p1;
}

// ---------------------------------------------------------------------------
// conv + silu: fp32 out (scan) + fp16 out (wx GEMM)
// ---------------------------------------------------------------------------
__global__ void __launch_bounds__(256) conv_silu_kernel(
    const float* __restrict__ xz, const float* __restrict__ w,
    const float* __restrict__ cb, float* __restrict__ out,
    __half* __restrict__ outh)
{
    int idx = blockIdx.x * 256 + threadIdx.x;
    int d = idx & (DINNER - 1);
    int t = idx >> 11;
    int l = t & (LSEQ - 1);
    float w0 = w[d * 4 + 0], w1 = w[d * 4 + 1], w2 = w[d * 4 + 2], w3 = w[d * 4 + 3];
    float s = cb[d];
    const float* base = xz + (size_t)t * (2 * DINNER) + d;
    if (l >= 3) s = fmaf(w0, base[-3 * (ptrdiff_t)(2 * DINNER)], s);
    if (l >= 2) s = fmaf(w1, base[-2 * (ptrdiff_t)(2 * DINNER)], s);
    if (l >= 1) s = fmaf(w2, base[-1 * (ptrdiff_t)(2 * DINNER)], s);
    s = fmaf(w3, base[0], s);
    float r = s / (1.f + expf(-s));
    out[idx]  = r;
    outh[idx] = __float2half_rn(r);
}

// ---------------------------------------------------------------------------
// selective scan, 8-deep prefetch ring; fp32 streams; B/C as one float2 load
// ---------------------------------------------------------------------------
#define PFD 8
__global__ void __launch_bounds__(256) scan_kernel(
    const float* __restrict__ dt, const float* __restrict__ xc,
    const float* __restrict__ dbc, const float* __restrict__ xz,
    const float* __restrict__ a_log, const float* __restrict__ d_skip,
    __half* __restrict__ y)
{
    int warp = threadIdx.x >> 5;
    int lane = threadIdx.x & 31;
    int half_ = lane >> 4;
    int n    = lane & 15;
    int gchan = blockIdx.x * 16 + warp * 2 + half_;
    int b = gchan >> 11;
    int d = gchan & (DINNER - 1);
    float Acoef = -expf(a_log[d * DSTATE + n]);
    float Dsk   = d_skip[d];
    float s = 0.f;
    int t0 = b * LSEQ;

    float dtb[PFD], xb[PFD], zb[PFD];
    float2 bcb[PFD];
    #pragma unroll
    for (int i = 0; i < PFD; i++) {
        int t = t0 + i;
        dtb[i] = dt [(size_t)t * DINNER + d];
        xb [i] = xc [(size_t)t * DINNER + d];
        bcb[i] = *(const float2*)(dbc + (size_t)t * NDBC + 64 + 2 * n);
        zb [i] = (n == 0) ? xz[(size_t)t * (2 * DINNER) + DINNER + d] : 0.f;
    }

    #pragma unroll 8
    for (int l = 0; l < LSEQ; l++) {
        int bi = l & (PFD - 1);
        float dt_c = dtb[bi], x_c = xb[bi], z_c = zb[bi];
        float2 bc = bcb[bi];
        int lp = l + PFD;
        if (lp < LSEQ) {
            int t2 = t0 + lp;
            dtb[bi] = dt [(size_t)t2 * DINNER + d];
            xb [bi] = xc [(size_t)t2 * DINNER + d];
            bcb[bi] = *(const float2*)(dbc + (size_t)t2 * NDBC + 64 + 2 * n);
            if (n == 0) zb[bi] = xz[(size_t)t2 * (2 * DINNER) + DINNER + d];
        }
        float dA = __expf(dt_c * Acoef);
        s = fmaf(s, dA, dt_c * x_c * bc.x);
        float part = s * bc.y;
        part += __shfl_down_sync(0xffffffffu, part, 8, 16);
        part += __shfl_down_sync(0xffffffffu, part, 4, 16);
        part += __shfl_down_sync(0xffffffffu, part, 2, 16);
        part += __shfl_down_sync(0xffffffffu, part, 1, 16);
        if (n == 0) {
            float yv = part + Dsk * x_c;
            yv = yv * (z_c / (1.f + __expf(-z_c)));
            y[(size_t)(t0 + l) * DINNER + d] = __float2half_rn(yv);
        }
    }
}

// ---------------------------------------------------------------------------
extern "C" void kernel_launch(void* const* d_in, const int* in_sizes, int n_in,
                              void* d_out, int out_size)
{
    const float* x      = (const float*)d_in[0];
    const float* ln1_g  = (const float*)d_in[1];
    const float* ln1_b  = (const float*)d_in[2];
    const float* w_in   = (const float*)d_in[3];
    const float* conv_w = (const float*)d_in[4];
    const float* conv_b = (const float*)d_in[5];
    const float* w_x    = (const float*)d_in[6];
    const float* w_dt   = (const float*)d_in[7];
    const float* b_dt   = (const float*)d_in[8];
    const float* a_log  = (const float*)d_in[9];
    const float* d_skip = (const float*)d_in[10];
    const float* w_out  = (const float*)d_in[11];
    const float* ln2_g  = (const float*)d_in[12];
    const float* ln2_b  = (const float*)d_in[13];
    const float* w_ff1  = (const float*)d_in[14];
    const float* b_ff1  = (const float*)d_in[15];
    const float* w_ff2  = (const float*)d_in[16];
    const float* b_ff2  = (const float*)d_in[17];
    float* out = (float*)d_out;

    __half *h, *xch, *dtlo, *y, *h2, *ffa;
    __half *wtin, *wtout, *wtff1, *wtff2, *wxt, *wdtt;
    float *xz, *xc, *dbc, *dtb, *out1;
    cudaGetSymbolAddress((void**)&h,     g_h);
    cudaGetSymbolAddress((void**)&xz,    g_xz);
    cudaGetSymbolAddress((void**)&xc,    g_xc);
    cudaGetSymbolAddress((void**)&xch,   g_xch);
    cudaGetSymbolAddress((void**)&dbc,   g_dbc);
    cudaGetSymbolAddress((void**)&dtlo,  g_dtlo);
    cudaGetSymbolAddress((void**)&dtb,   g_dt);
    cudaGetSymbolAddress((void**)&y,     g_y);
    cudaGetSymbolAddress((void**)&out1,  g_out1);
    cudaGetSymbolAddress((void**)&h2,    g_h2);
    cudaGetSymbolAddress((void**)&ffa,   g_ffa);
    cudaGetSymbolAddress((void**)&wtin,  g_wtin);
    cudaGetSymbolAddress((void**)&wtout, g_wtout);
    cudaGetSymbolAddress((void**)&wtff1, g_wtff1);
    cudaGetSymbolAddress((void**)&wtff2, g_wtff2);
    cudaGetSymbolAddress((void**)&wxt,   g_wxt);
    cudaGetSymbolAddress((void**)&wdtt,  g_wdtt);

    cudaFuncSetAttribute(mh_gemm<0>, cudaFuncAttributeMaxDynamicSharedMemorySize, MH_SMEM);
    cudaFuncSetAttribute(mh_gemm<2>, cudaFuncAttributeMaxDynamicSharedMemorySize, MH_SMEM);
    cudaFuncSetAttribute(mh_gemm<3>, cudaFuncAttributeMaxDynamicSharedMemorySize, MH_SMEM);
    cudaFuncSetAttribute(mh_gemm<5>, cudaFuncAttributeMaxDynamicSharedMemorySize, MH_SMEM);
    cudaFuncSetAttribute(fg_gemm,    cudaFuncAttributeMaxDynamicSharedMemorySize, FG_SMEM);
    cudaFuncSetAttribute(wx_tc,      cudaFuncAttributeMaxDynamicSharedMemorySize, WX_SMEM);

    // 1. ALL weight transposes in one launch (18752 blocks)
    transpose_m6<<<18752, 256>>>(
        w_in,  wtin,  1024, 4096, 128, 4096,
        w_out, wtout, 2048, 1024, 32,  6144,
        w_x,   wxt,   2048, 96,   3,   6336,
        w_dt,  wdtt,  64,   2048, 64,  6464,
        w_ff1, wtff1, 1024, 8192, 256, 14656,
        w_ff2, wtff2, 4096, 1024, 32);
    // 2. ln1 (fp16 out)
    ln_kernel<<<TOKENS, 256>>>(x, ln1_g, ln1_b, h);
    // 3. xz = h @ w_in
    mh_gemm<0><<<dim3(4096 / BN, TOKENS / BM), 256, MH_SMEM>>>(
        h, wtin, xz, nullptr, nullptr, 1024, 4096);
    // 4. conv + silu  [ncu-sampled slot this round]
    conv_silu_kernel<<<(TOKENS * DINNER) / 256, 256>>>(xz, conv_w, conv_b, xc, xch);
    // 5. dbc = xch @ w_x^T (interleaved B/C) + fp16 dt_lo copy
    wx_tc<<<dim3(1, TOKENS / 64), 256, WX_SMEM>>>(xch, wxt, dbc, dtlo);
    // 6. dt = softplus(dt_lo @ w_dt + b_dt)
    mh_gemm<5><<<dim3(DINNER / BN, TOKENS / BM), 256, MH_SMEM>>>(
        dtlo, wdtt, dtb, b_dt, nullptr, 64, DINNER);
    // 7. scan
    scan_kernel<<<(2 * DINNER) / 16, 256>>>(dtb, xc, dbc, xz, a_log, d_skip, y);
    // 8. out1 = x + y @ w_out
    mh_gemm<2><<<dim3(DMODEL / BN, TOKENS / BM), 256, MH_SMEM>>>(
        y, wtout, out1, nullptr, x, 2048, DMODEL);
    // 9. ln2
    ln_kernel<<<TOKENS, 256>>>(out1, ln2_g, ln2_b, h2);
    // 10. fused ff1 + geglu
    fg_gemm<<<dim3(FFIN / 64, TOKENS / BM), 256, FG_SMEM>>>(
        h2, wtff1, ffa, b_ff1, 1024);
    // 11. out = out1 + ffa @ w_ff2 + b_ff2
    mh_gemm<3><<<dim3(DMODEL / BN, TOKENS / BM), 256, MH_SMEM>>>(
        ffa, wtff2, out, b_ff2, out1, FFIN, DMODEL);
}

// round 15
// speedup vs baseline: 1.1149x; 1.0783x over previous
#include <cuda_runtime.h>
#include <cuda_fp16.h>
#include <math.h>
#include <stdint.h>

#define TOKENS   4096
#define DMODEL   1024
#define DINNER   2048
#define DSTATE   16
#define DTRANK   64
#define FFIN     4096
#define LSEQ     2048
#define NDBC     128
#define NSEG     8
#define SEGL     256        // LSEQ / NSEG

// ---------------- scratch ----------------
__device__ __align__(128) __half g_h    [TOKENS * DMODEL];
__device__ __align__(128) float  g_xz   [TOKENS * 2 * DINNER];
__device__ __align__(128) float  g_xc   [TOKENS * DINNER];
__device__ __align__(128) __half g_xch  [TOKENS * DINNER];
__device__ __align__(128) float  g_dbc  [TOKENS * NDBC];   // cols 64..95: B0,C0,B1,C1,...
__device__ __align__(128) __half g_dtlo [TOKENS * DTRANK];
__device__ __align__(128) float  g_dt   [TOKENS * DINNER];
__device__ __align__(128) __half g_y    [TOKENS * DINNER];
__device__ __align__(128) float  g_out1 [TOKENS * DMODEL];
__device__ __align__(128) __half g_h2   [TOKENS * DMODEL];
__device__ __align__(128) __half g_ffa  [TOKENS * FFIN];
__device__ __align__(128) __half g_wtin [4096 * 1024];
__device__ __align__(128) __half g_wtout[1024 * 2048];
__device__ __align__(128) __half g_wtff1[8192 * 1024];
__device__ __align__(128) __half g_wtff2[1024 * 4096];
__device__ __align__(128) __half g_wxt  [128 * 2048];
__device__ __align__(128) __half g_wdtt [2048 * 64];
// chunked-scan buffers: [seg][gchan][n]
__device__ __align__(128) float  g_sf [7 * 4096 * DSTATE];
__device__ __align__(128) float  g_sp [7 * 4096 * DSTATE];
__device__ __align__(128) float  g_si [8 * 4096 * DSTATE];

// ---------------- helpers ----------------
__device__ __forceinline__ float softplus_f(float x) {
    return (x > 20.f) ? x : log1pf(expf(x));
}
__device__ __forceinline__ float tanh_ap(float x) {
    float r;
    asm("tanh.approx.f32 %0, %1;" : "=f"(r) : "f"(x));
    return r;
}
__device__ __forceinline__ float gelu_t(float g) {
    float u = 0.7978845608028654f * fmaf(0.044715f * g * g, g, g);
    return 0.5f * g * (1.f + tanh_ap(u));
}
__device__ __forceinline__ uint32_t smem_u32(const void* p) {
    uint32_t a;
    asm("{ .reg .u64 t; cvta.to.shared.u64 t, %1; cvt.u32.u64 %0, t; }" : "=r"(a) : "l"(p));
    return a;
}
__device__ __forceinline__ void cp16(uint32_t dst, const void* src) {
    asm volatile("cp.async.cg.shared.global [%0], [%1], 16;" :: "r"(dst), "l"(src));
}
#define CP_COMMIT() asm volatile("cp.async.commit_group;" ::: "memory")
#define CP_WAIT0()  asm volatile("cp.async.wait_group 0;" ::: "memory")
#define CP_WAIT1()  asm volatile("cp.async.wait_group 1;" ::: "memory")

__device__ __forceinline__ void ldm_x4(uint32_t& r0, uint32_t& r1,
                                       uint32_t& r2, uint32_t& r3, uint32_t addr)
{
    asm volatile("ldmatrix.sync.aligned.m8n8.x4.shared.b16 {%0,%1,%2,%3}, [%4];"
                 : "=r"(r0), "=r"(r1), "=r"(r2), "=r"(r3) : "r"(addr));
}
__device__ __forceinline__ void mma_f16(
    float& c0, float& c1, float& c2, float& c3,
    uint32_t a0, uint32_t a1, uint32_t a2, uint32_t a3,
    uint32_t b0, uint32_t b1)
{
    asm volatile(
        "mma.sync.aligned.m16n8k16.row.col.f32.f16.f16.f32 "
        "{%0,%1,%2,%3}, {%4,%5,%6,%7}, {%8,%9}, {%0,%1,%2,%3};"
        : "+f"(c0), "+f"(c1), "+f"(c2), "+f"(c3)
        : "r"(a0), "r"(a1), "r"(a2), "r"(a3), "r"(b0), "r"(b1));
}

// ---------------------------------------------------------------------------
// fp16 tensor GEMM: C[M,N] = A[M,K] @ Bw[N,K]^T, 128x128 tile, 3-stage pipe.
// MODE bits: 1 = +bias[n], 2 = +res[m,n], 4 = softplus
// ---------------------------------------------------------------------------
#define BM 128
#define BN 128
#define BKH 64
#define LDH 72
#define HSTG ((BM + BN) * LDH)
#define MH_SMEM (3 * HSTG * 2)

__device__ __forceinline__ void mh_load(
    const __half* __restrict__ A, const __half* __restrict__ Bw, int K,
    int m0, int n0, uint32_t sbyte, int stage, int chunk, int tid)
{
    uint32_t ab = sbyte + (uint32_t)stage * (HSTG * 2);
    uint32_t bb = ab + BM * LDH * 2;
    const __half* Ap = A  + (size_t)m0 * K + chunk * BKH;
    const __half* Bp = Bw + (size_t)n0 * K + chunk * BKH;
    #pragma unroll
    for (int p = 0; p < 4; p++) {
        int idx = tid + (p << 8);
        int r = idx >> 3, c = idx & 7;
        cp16(ab + (uint32_t)(r * LDH + c * 8) * 2, Ap + (size_t)r * K + c * 8);
    }
    #pragma unroll
    for (int p = 0; p < 4; p++) {
        int idx = tid + (p << 8);
        int r = idx >> 3, c = idx & 7;
        cp16(bb + (uint32_t)(r * LDH + c * 8) * 2, Bp + (size_t)r * K + c * 8);
    }
}

template <int MODE>
__global__ void __launch_bounds__(256, 2) mh_gemm(
    const __half* __restrict__ A, const __half* __restrict__ Bw,
    float* __restrict__ C, const float* __restrict__ bias,
    const float* __restrict__ res, int K, int N)
{
    extern __shared__ char smraw[];
    const uint32_t sbyte = smem_u32(smraw);
    const int tid  = threadIdx.x;
    const int lane = tid & 31;
    const int wid  = tid >> 5;
    const int wm   = wid >> 1;
    const int wn   = wid & 1;
    const int row  = lane >> 2;
    const int qc   = lane & 3;
    const int m0 = blockIdx.y * BM;
    const int n0 = blockIdx.x * BN;

    const int a_r  = ((lane >> 3) & 1) * 8 + (lane & 7);
    const int a_k  = (lane >> 4) * 8;
    const int b_r  = (lane >> 4) * 8 + (lane & 7);
    const int b_k  = ((lane >> 3) & 1) * 8;

    float acc[2][8][4];
    #pragma unroll
    for (int i = 0; i < 2; i++)
        #pragma unroll
        for (int j = 0; j < 8; j++)
            #pragma unroll
            for (int q = 0; q < 4; q++) acc[i][j][q] = 0.f;

    const int nc = K / BKH;
    mh_load(A, Bw, K, m0, n0, sbyte, 0, 0, tid);
    CP_COMMIT();
    if (1 < nc) mh_load(A, Bw, K, m0, n0, sbyte, 1, 1, tid);
    CP_COMMIT();

    int stage = 0;
    for (int ks = 0; ks < nc; ks++) {
        if (ks + 1 < nc) { CP_WAIT1(); } else { CP_WAIT0(); }
        __syncthreads();
        int ldst = stage + 2; if (ldst >= 3) ldst -= 3;
        if (ks + 2 < nc)
            mh_load(A, Bw, K, m0, n0, sbyte, ldst, ks + 2, tid);
        CP_COMMIT();

        uint32_t as_ = sbyte + (uint32_t)stage * (HSTG * 2);
        uint32_t bs_ = as_ + BM * LDH * 2;
        #pragma unroll
        for (int kk = 0; kk < 4; kk++) {
            int k = kk * 16;
            uint32_t a[2][4];
            #pragma unroll
            for (int mt = 0; mt < 2; mt++) {
                int r = wm * 32 + mt * 16 + a_r;
                ldm_x4(a[mt][0], a[mt][1], a[mt][2], a[mt][3],
                       as_ + (uint32_t)(r * LDH + k + a_k) * 2);
            }
            uint32_t b[8][2];
            #pragma unroll
            for (int q = 0; q < 4; q++) {
                int r = wn * 64 + q * 16 + b_r;
                uint32_t t0, t1, t2, t3;
                ldm_x4(t0, t1, t2, t3,
                       bs_ + (uint32_t)(r * LDH + k + b_k) * 2);
                b[2 * q][0] = t0;  b[2 * q][1] = t1;
                b[2 * q + 1][0] = t2;  b[2 * q + 1][1] = t3;
            }
            #pragma unroll
            for (int mt = 0; mt < 2; mt++)
                #pragma unroll
                for (int nt = 0; nt < 8; nt++)
                    mma_f16(acc[mt][nt][0], acc[mt][nt][1],
                            acc[mt][nt][2], acc[mt][nt][3],
                            a[mt][0], a[mt][1], a[mt][2], a[mt][3],
                            b[nt][0], b[nt][1]);
        }
        stage++; if (stage >= 3) stage -= 3;
    }

    #pragma unroll
    for (int mt = 0; mt < 2; mt++) {
        int gr0 = m0 + wm * 32 + mt * 16 + row;
        #pragma unroll
        for (int nt = 0; nt < 8; nt++) {
            int gc = n0 + wn * 64 + nt * 8 + qc * 2;
            float2 v0 = make_float2(acc[mt][nt][0], acc[mt][nt][1]);
            float2 v1 = make_float2(acc[mt][nt][2], acc[mt][nt][3]);
            if (MODE & 1) {
                float2 bb = *(const float2*)(bias + gc);
                v0.x += bb.x; v0.y += bb.y;
                v1.x += bb.x; v1.y += bb.y;
            }
            if (MODE & 4) {
                v0.x = softplus_f(v0.x); v0.y = softplus_f(v0.y);
                v1.x = softplus_f(v1.x); v1.y = softplus_f(v1.y);
            }
            if (MODE & 2) {
                float2 r0 = *(const float2*)(res + (size_t)gr0 * N + gc);
                float2 r1 = *(const float2*)(res + (size_t)(gr0 + 8) * N + gc);
                v0.x += r0.x; v0.y += r0.y;
                v1.x += r1.x; v1.y += r1.y;
            }
            *(float2*)(C + (size_t)gr0 * N + gc)       = v0;
            *(float2*)(C + (size_t)(gr0 + 8) * N + gc) = v1;
        }
    }
}

// ---------------------------------------------------------------------------
// wx tensor GEMM: dbc[M,128] = xch[M,2048] @ wxt[128,2048]^T (B/C interleaved)
// ---------------------------------------------------------------------------
#define WXSTG ((64 + 128) * LDH)
#define WX_SMEM (2 * WXSTG * 2)

__device__ __forceinline__ void wx_load(
    const __half* __restrict__ A, const __half* __restrict__ Bw,
    int m0, uint32_t sbyte, int stage, int chunk, int tid)
{
    uint32_t ab = sbyte + (uint32_t)stage * (WXSTG * 2);
    uint32_t bb = ab + 64 * LDH * 2;
    const __half* Ap = A  + (size_t)m0 * DINNER + chunk * BKH;
    const __half* Bp = Bw + chunk * BKH;
    #pragma unroll
    for (int p = 0; p < 2; p++) {
        int idx = tid + (p << 8);
        int r = idx >> 3, c = idx & 7;
        cp16(ab + (uint32_t)(r * LDH + c * 8) * 2, Ap + (size_t)r * DINNER + c * 8);
    }
    #pragma unroll
    for (int p = 0; p < 4; p++) {
        int idx = tid + (p << 8);
        int r = idx >> 3, c = idx & 7;
        cp16(bb + (uint32_t)(r * LDH + c * 8) * 2, Bp + (size_t)r * DINNER + c * 8);
    }
}

__device__ __forceinline__ int dbc_col(int c) {
    if (c < 64) return c;
    if (c < 80) return 64 + 2 * (c - 64);       // B_n
    return 64 + 2 * (c - 80) + 1;               // C_n
}

__global__ void __launch_bounds__(256, 2) wx_tc(
    const __half* __restrict__ A, const __half* __restrict__ Bw,
    float* __restrict__ dbc, __half* __restrict__ dtlo)
{
    extern __shared__ char smraw[];
    const uint32_t sbyte = smem_u32(smraw);
    const int tid  = threadIdx.x;
    const int lane = tid & 31;
    const int wid  = tid >> 5;
    const int wm   = wid >> 2;
    const int wn   = wid & 3;
    const int row  = lane >> 2;
    const int qc   = lane & 3;
    const int m0 = blockIdx.y * 64;

    const int a_r  = ((lane >> 3) & 1) * 8 + (lane & 7);
    const int a_k  = (lane >> 4) * 8;
    const int b_r  = (lane >> 4) * 8 + (lane & 7);
    const int b_k  = ((lane >> 3) & 1) * 8;

    float acc[2][4][4];
    #pragma unroll
    for (int i = 0; i < 2; i++)
        #pragma unroll
        for (int j = 0; j < 4; j++)
            #pragma unroll
            for (int q = 0; q < 4; q++) acc[i][j][q] = 0.f;

    const int nc = DINNER / BKH;
    wx_load(A, Bw, m0, sbyte, 0, 0, tid);
    CP_COMMIT();

    for (int ks = 0; ks < nc; ks++) {
        if (ks + 1 < nc) {
            wx_load(A, Bw, m0, sbyte, (ks + 1) & 1, ks + 1, tid);
            CP_COMMIT();
            CP_WAIT1();
        } else {
            CP_WAIT0();
        }
        __syncthreads();

        uint32_t as_ = sbyte + (uint32_t)(ks & 1) * (WXSTG * 2);
        uint32_t bs_ = as_ + 64 * LDH * 2;
        #pragma unroll
        for (int kk = 0; kk < 4; kk++) {
            int k = kk * 16;
            uint32_t a[2][4];
            #pragma unroll
            for (int mt = 0; mt < 2; mt++) {
                int r = wm * 32 + mt * 16 + a_r;
                ldm_x4(a[mt][0], a[mt][1], a[mt][2], a[mt][3],
                       as_ + (uint32_t)(r * LDH + k + a_k) * 2);
            }
            uint32_t b[4][2];
            #pragma unroll
            for (int q = 0; q < 2; q++) {
                int r = wn * 32 + q * 16 + b_r;
                uint32_t t0, t1, t2, t3;
                ldm_x4(t0, t1, t2, t3, bs_ + (uint32_t)(r * LDH + k + b_k) * 2);
                b[2 * q][0] = t0;  b[2 * q][1] = t1;
                b[2 * q + 1][0] = t2;  b[2 * q + 1][1] = t3;
            }
            #pragma unroll
            for (int mt = 0; mt < 2; mt++)
                #pragma unroll
                for (int nt = 0; nt < 4; nt++)
                    mma_f16(acc[mt][nt][0], acc[mt][nt][1],
                            acc[mt][nt][2], acc[mt][nt][3],
                            a[mt][0], a[mt][1], a[mt][2], a[mt][3],
                            b[nt][0], b[nt][1]);
        }
        __syncthreads();
    }

    #pragma unroll
    for (int mt = 0; mt < 2; mt++) {
        int gr0 = m0 + wm * 32 + mt * 16 + row;
        #pragma unroll
        for (int nt = 0; nt < 4; nt++) {
            int gc = wn * 32 + nt * 8 + qc * 2;
            float2 v0 = make_float2(acc[mt][nt][0], acc[mt][nt][1]);
            float2 v1 = make_float2(acc[mt][nt][2], acc[mt][nt][3]);
            dbc[(size_t)gr0 * NDBC + dbc_col(gc)]           = v0.x;
            dbc[(size_t)gr0 * NDBC + dbc_col(gc + 1)]       = v0.y;
            dbc[(size_t)(gr0 + 8) * NDBC + dbc_col(gc)]     = v1.x;
            dbc[(size_t)(gr0 + 8) * NDBC + dbc_col(gc + 1)] = v1.y;
            if (gc < DTRANK) {
                ((__half2*)(dtlo + (size_t)gr0 * DTRANK))[gc >> 1] =
                    __floats2half2_rn(v0.x, v0.y);
                ((__half2*)(dtlo + (size_t)(gr0 + 8) * DTRANK))[gc >> 1] =
                    __floats2half2_rn(v1.x, v1.y);
            }
        }
    }
}

// ---------------------------------------------------------------------------
// Fused ff1 + geglu, 128x64 tile, 3-stage pipeline
// ---------------------------------------------------------------------------
#define FG_SMEM MH_SMEM

__device__ __forceinline__ void fg_load(
    const __half* __restrict__ A, const __half* __restrict__ Bw, int K,
    int m0, int n0, uint32_t sbyte, int stage, int chunk, int tid)
{
    uint32_t ab  = sbyte + (uint32_t)stage * (HSTG * 2);
    uint32_t bab = ab  + BM * LDH * 2;
    uint32_t bgb = bab + 64 * LDH * 2;
    const __half* Ap  = A  + (size_t)m0 * K + chunk * BKH;
    const __half* Bap = Bw + (size_t)n0 * K + chunk * BKH;
    const __half* Bgp = Bw + (size_t)(4096 + n0) * K + chunk * BKH;
    #pragma unroll
    for (int p = 0; p < 4; p++) {
        int idx = tid + (p << 8);
        int r = idx >> 3, c = idx & 7;
        cp16(ab + (uint32_t)(r * LDH + c * 8) * 2, Ap + (size_t)r * K + c * 8);
    }
    #pragma unroll
    for (int p = 0; p < 2; p++) {
        int idx = tid + (p << 8);
        int r = idx >> 3, c = idx & 7;
        cp16(bab + (uint32_t)(r * LDH + c * 8) * 2, Bap + (size_t)r * K + c * 8);
    }
    #pragma unroll
    for (int p = 0; p < 2; p++) {
        int idx = tid + (p << 8);
        int r = idx >> 3, c = idx & 7;
        cp16(bgb + (uint32_t)(r * LDH + c * 8) * 2, Bgp + (size_t)r * K + c * 8);
    }
}

__global__ void __launch_bounds__(256, 2) fg_gemm(
    const __half* __restrict__ A, const __half* __restrict__ Bw,
    __half* __restrict__ out, const float* __restrict__ bias, int K)
{
    extern __shared__ char smraw[];
    const uint32_t sbyte = smem_u32(smraw);
    const int tid  = threadIdx.x;
    const int lane = tid & 31;
    const int wid  = tid >> 5;
    const int wm   = wid >> 1;
    const int wn   = wid & 1;
    const int row  = lane >> 2;
    const int qc   = lane & 3;
    const int m0 = blockIdx.y * BM;
    const int n0 = blockIdx.x * 64;

    const int a_r  = ((lane >> 3) & 1) * 8 + (lane & 7);
    const int a_k  = (lane >> 4) * 8;
    const int b_r  = (lane >> 4) * 8 + (lane & 7);
    const int b_k  = ((lane >> 3) & 1) * 8;

    float acca[2][4][4], accg[2][4][4];
    #pragma unroll
    for (int i = 0; i < 2; i++)
        #pragma unroll
        for (int j = 0; j < 4; j++)
            #pragma unroll
            for (int q = 0; q < 4; q++) { acca[i][j][q] = 0.f; accg[i][j][q] = 0.f; }

    const int nc = K / BKH;
    fg_load(A, Bw, K, m0, n0, sbyte, 0, 0, tid);
    CP_COMMIT();
    if (1 < nc) fg_load(A, Bw, K, m0, n0, sbyte, 1, 1, tid);
    CP_COMMIT();

    int stage = 0;
    for (int ks = 0; ks < nc; ks++) {
        if (ks + 1 < nc) { CP_WAIT1(); } else { CP_WAIT0(); }
        __syncthreads();
        int ldst = stage + 2; if (ldst >= 3) ldst -= 3;
        if (ks + 2 < nc)
            fg_load(A, Bw, K, m0, n0, sbyte, ldst, ks + 2, tid);
        CP_COMMIT();

        uint32_t as_ = sbyte + (uint32_t)stage * (HSTG * 2);
        uint32_t ba_ = as_ + BM * LDH * 2;
        uint32_t bg_ = ba_ + 64 * LDH * 2;
        #pragma unroll
        for (int kk = 0; kk < 4; kk++) {
            int k = kk * 16;
            uint32_t a[2][4];
            #pragma unroll
            for (int mt = 0; mt < 2; mt++) {
                int r = wm * 32 + mt * 16 + a_r;
                ldm_x4(a[mt][0], a[mt][1], a[mt][2], a[mt][3],
                       as_ + (uint32_t)(r * LDH + k + a_k) * 2);
            }
            uint32_t ba[4][2], bg[4][2];
            #pragma unroll
            for (int q = 0; q < 2; q++) {
                int r = wn * 32 + q * 16 + b_r;
                uint32_t t0, t1, t2, t3;
                ldm_x4(t0, t1, t2, t3, ba_ + (uint32_t)(r * LDH + k + b_k) * 2);
                ba[2 * q][0] = t0;  ba[2 * q][1] = t1;
                ba[2 * q + 1][0] = t2;  ba[2 * q + 1][1] = t3;
                ldm_x4(t0, t1, t2, t3, bg_ + (uint32_t)(r * LDH + k + b_k) * 2);
                bg[2 * q][0] = t0;  bg[2 * q][1] = t1;
                bg[2 * q + 1][0] = t2;  bg[2 * q + 1][1] = t3;
            }
            #pragma unroll
            for (int mt = 0; mt < 2; mt++)
                #pragma unroll
                for (int nt = 0; nt < 4; nt++) {
                    mma_f16(acca[mt][nt][0], acca[mt][nt][1],
                            acca[mt][nt][2], acca[mt][nt][3],
                            a[mt][0], a[mt][1], a[mt][2], a[mt][3],
                            ba[nt][0], ba[nt][1]);
                    mma_f16(accg[mt][nt][0], accg[mt][nt][1],
                            accg[mt][nt][2], accg[mt][nt][3],
                            a[mt][0], a[mt][1], a[mt][2], a[mt][3],
                            bg[nt][0], bg[nt][1]);
                }
        }
        stage++; if (stage >= 3) stage -= 3;
    }

    #pragma unroll
    for (int mt = 0; mt < 2; mt++) {
        int gr0 = m0 + wm * 32 + mt * 16 + row;
        #pragma unroll
        for (int nt = 0; nt < 4; nt++) {
            int gc = n0 + wn * 32 + nt * 8 + qc * 2;
            float2 bba = *(const float2*)(bias + gc);
            float2 bbg = *(const float2*)(bias + 4096 + gc);
            float a0 = acca[mt][nt][0] + bba.x, a1 = acca[mt][nt][1] + bba.y;
            float g0 = accg[mt][nt][0] + bbg.x, g1 = accg[mt][nt][1] + bbg.y;
            float a2 = acca[mt][nt][2] + bba.x, a3 = acca[mt][nt][3] + bba.y;
            float g2 = accg[mt][nt][2] + bbg.x, g3 = accg[mt][nt][3] + bbg.y;
            ((__half2*)(out + (size_t)gr0 * FFIN))[gc >> 1] =
                __floats2half2_rn(a0 * gelu_t(g0), a1 * gelu_t(g1));
            ((__half2*)(out + (size_t)(gr0 + 8) * FFIN))[gc >> 1] =
                __floats2half2_rn(a2 * gelu_t(g2), a3 * gelu_t(g3));
        }
    }
}

// ---------------------------------------------------------------------------
// 6-segment transpose fp32[K,N] -> fp16[N,K]
// ---------------------------------------------------------------------------
__global__ void __launch_bounds__(256) transpose_m6(
    const float* in0, __half* out0, int K0, int N0, int gx0, int c1,
    const float* in1, __half* out1, int K1, int N1, int gx1, int c2,
    const float* in2, __half* out2, int K2, int N2, int gx2, int c3,
    const float* in3, __half* out3, int K3, int N3, int gx3, int c4,
    const float* in4, __half* out4, int K4, int N4, int gx4, int c5,
    const float* in5, __half* out5, int K5, int N5, int gx5)
{
    int b = blockIdx.x;
    const float* in; __half* out; int K, N, gx, local;
    if (b < c1)      { in = in0; out = out0; K = K0; N = N0; gx = gx0; local = b; }
    else if (b < c2) { in = in1; out = out1; K = K1; N = N1; gx = gx1; local = b - c1; }
    else if (b < c3) { in = in2; out = out2; K = K2; N = N2; gx = gx2; local = b - c2; }
    else if (b < c4) { in = in3; out = out3; K = K3; N = N3; gx = gx3; local = b - c3; }
    else if (b < c5) { in = in4; out = out4; K = K4; N = N4; gx = gx4; local = b - c4; }
    else             { in = in5; out = out5; K = K5; N = N5; gx = gx5; local = b - c5; }
    int n0 = (local % gx) * 32;
    int k0 = (local / gx) * 32;

    __shared__ float t[32][33];
    int x = threadIdx.x & 31, y = threadIdx.x >> 5;
    #pragma unroll
    for (int i = 0; i < 4; i++)
        t[y + 8 * i][x] = in[(size_t)(k0 + y + 8 * i) * N + n0 + x];
    __syncthreads();
    #pragma unroll
    for (int i = 0; i < 4; i++)
        out[(size_t)(n0 + y + 8 * i) * K + k0 + x] = __float2half_rn(t[x][y + 8 * i]);
}

// ---------------------------------------------------------------------------
__global__ void __launch_bounds__(256) ln_kernel(
    const float* __restrict__ x, const float* __restrict__ g,
    const float* __restrict__ b, __half* __restrict__ out)
{
    int t = blockIdx.x, tid = threadIdx.x;
    float4 v = ((const float4*)(x + (size_t)t * DMODEL))[tid];
    float s  = v.x + v.y + v.z + v.w;
    float ss = fmaf(v.x, v.x, fmaf(v.y, v.y, fmaf(v.z, v.z, v.w * v.w)));
    #pragma unroll
    for (int o = 16; o > 0; o >>= 1) {
        s  += __shfl_down_sync(0xffffffffu, s, o);
        ss += __shfl_down_sync(0xffffffffu, ss, o);
    }
    __shared__ float rs_[8], rss_[8];
    __shared__ float smu, srs;
    int warp = tid >> 5, lane = tid & 31;
    if (lane == 0) { rs_[warp] = s; rss_[warp] = ss; }
    __syncthreads();
    if (tid == 0) {
        float S = 0.f, SS = 0.f;
        #pragma unroll
        for (int w = 0; w < 8; w++) { S += rs_[w]; SS += rss_[w]; }
        float mu = S * (1.f / DMODEL);
        smu = mu;
        srs = rsqrtf(SS * (1.f / DMODEL) - mu * mu + 1e-5f);
    }
    __syncthreads();
    float mu = smu, rs = srs;
    float4 gv = ((const float4*)g)[tid];
    float4 bv = ((const float4*)b)[tid];
    __half2 p0 = __floats2half2_rn((v.x - mu) * rs * gv.x + bv.x,
                                   (v.y - mu) * rs * gv.y + bv.y);
    __half2 p1 = __floats2half2_rn((v.z - mu) * rs * gv.z + bv.z,
                                   (v.w - mu) * rs * gv.w + bv.w);
    __half2* orow = (__half2*)(out + (size_t)t * DMODEL);
    orow[2 * tid]     = p0;
    orow[2 * tid + 1] = p1;
}

// ---------------------------------------------------------------------------
// conv + silu: fp32 out (scan) + fp16 out (wx GEMM)
// ---------------------------------------------------------------------------
__global__ void __launch_bounds__(256) conv_silu_kernel(
    const float* __restrict__ xz, const float* __restrict__ w,
    const float* __restrict__ cb, float* __restrict__ out,
    __half* __restrict__ outh)
{
    int idx = blockIdx.x * 256 + threadIdx.x;
    int d = idx & (DINNER - 1);
    int t = idx >> 11;
    int l = t & (LSEQ - 1);
    float w0 = w[d * 4 + 0], w1 = w[d * 4 + 1], w2 = w[d * 4 + 2], w3 = w[d * 4 + 3];
    float s = cb[d];
    const float* base = xz + (size_t)t * (2 * DINNER) + d;
    if (l >= 3) s = fmaf(w0, base[-3 * (ptrdiff_t)(2 * DINNER)], s);
    if (l >= 2) s = fmaf(w1, base[-2 * (ptrdiff_t)(2 * DINNER)], s);
    if (l >= 1) s = fmaf(w2, base[-1 * (ptrdiff_t)(2 * DINNER)], s);
    s = fmaf(w3, base[0], s);
    float r = s / (1.f + expf(-s));
    out[idx]  = r;
    outh[idx] = __float2half_rn(r);
}

// ---------------------------------------------------------------------------
// chunked selective scan (3 passes)
// pass A: per-segment local scan (init 0): f = final state, p = prod(dA)
// ---------------------------------------------------------------------------
#define PFD 8
__global__ void __launch_bounds__(256) scan_partial(
    const float* __restrict__ dt, const float* __restrict__ xc,
    const float* __restrict__ dbc, const float* __restrict__ a_log,
    float* __restrict__ sf, float* __restrict__ sp)
{
    int seg  = blockIdx.y;                       // 0..6
    int warp = threadIdx.x >> 5;
    int lane = threadIdx.x & 31;
    int half_ = lane >> 4;
    int n    = lane & 15;
    int gchan = blockIdx.x * 16 + warp * 2 + half_;
    int b = gchan >> 11;
    int d = gchan & (DINNER - 1);
    float Acoef = -expf(a_log[d * DSTATE + n]);
    int t0 = b * LSEQ + seg * SEGL;

    float s = 0.f, p = 1.f;
    float dtb[PFD], xb[PFD], Bb[PFD];
    #pragma unroll
    for (int i = 0; i < PFD; i++) {
        int t = t0 + i;
        dtb[i] = dt [(size_t)t * DINNER + d];
        xb [i] = xc [(size_t)t * DINNER + d];
        Bb [i] = dbc[(size_t)t * NDBC + 64 + 2 * n];
    }
    #pragma unroll 8
    for (int l = 0; l < SEGL; l++) {
        int bi = l & (PFD - 1);
        float dt_c = dtb[bi], x_c = xb[bi], B_c = Bb[bi];
        int lp = l + PFD;
        if (lp < SEGL) {
            int t2 = t0 + lp;
            dtb[bi] = dt [(size_t)t2 * DINNER + d];
            xb [bi] = xc [(size_t)t2 * DINNER + d];
            Bb [bi] = dbc[(size_t)t2 * NDBC + 64 + 2 * n];
        }
        float dA = __expf(dt_c * Acoef);
        p *= dA;
        s = fmaf(s, dA, dt_c * x_c * B_c);
    }
    size_t o = ((size_t)seg * 4096 + gchan) * DSTATE + n;
    sf[o] = s;
    sp[o] = p;
}

// pass B: sequential combine across segments (tiny)
__global__ void __launch_bounds__(256) scan_combine(
    const float* __restrict__ sf, const float* __restrict__ sp,
    float* __restrict__ si)
{
    int idx = blockIdx.x * 256 + threadIdx.x;    // < 4096*16
    float s = 0.f;
    #pragma unroll
    for (int seg = 0; seg < NSEG; seg++) {
        si[(size_t)seg * (4096 * DSTATE) + idx] = s;
        if (seg < NSEG - 1)
            s = fmaf(sp[(size_t)seg * (4096 * DSTATE) + idx], s,
                     sf[(size_t)seg * (4096 * DSTATE) + idx]);
    }
}

// pass C: per-segment scan with correct init; full epilogue
__global__ void __launch_bounds__(256) scan_final(
    const float* __restrict__ dt, const float* __restrict__ xc,
    const float* __restrict__ dbc, const float* __restrict__ xz,
    const float* __restrict__ a_log, const float* __restrict__ d_skip,
    const float* __restrict__ si, __half* __restrict__ y)
{
    int seg  = blockIdx.y;                       // 0..7
    int warp = threadIdx.x >> 5;
    int lane = threadIdx.x & 31;
    int half_ = lane >> 4;
    int n    = lane & 15;
    int gchan = blockIdx.x * 16 + warp * 2 + half_;
    int b = gchan >> 11;
    int d = gchan & (DINNER - 1);
    float Acoef = -expf(a_log[d * DSTATE + n]);
    float Dsk   = d_skip[d];
    int t0 = b * LSEQ + seg * SEGL;
    float s = si[((size_t)seg * 4096 + gchan) * DSTATE + n];

    float dtb[PFD], xb[PFD], zb[PFD];
    float2 bcb[PFD];
    #pragma unroll
    for (int i = 0; i < PFD; i++) {
        int t = t0 + i;
        dtb[i] = dt [(size_t)t * DINNER + d];
        xb [i] = xc [(size_t)t * DINNER + d];
        bcb[i] = *(const float2*)(dbc + (size_t)t * NDBC + 64 + 2 * n);
        zb [i] = (n == 0) ? xz[(size_t)t * (2 * DINNER) + DINNER + d] : 0.f;
    }
    #pragma unroll 8
    for (int l = 0; l < SEGL; l++) {
        int bi = l & (PFD - 1);
        float dt_c = dtb[bi], x_c = xb[bi], z_c = zb[bi];
        float2 bc = bcb[bi];
        int lp = l + PFD;
        if (lp < SEGL) {
            int t2 = t0 + lp;
            dtb[bi] = dt [(size_t)t2 * DINNER + d];
            xb [bi] = xc [(size_t)t2 * DINNER + d];
            bcb[bi] = *(const float2*)(dbc + (size_t)t2 * NDBC + 64 + 2 * n);
            if (n == 0) zb[bi] = xz[(size_t)t2 * (2 * DINNER) + DINNER + d];
        }
        float dA = __expf(dt_c * Acoef);
        s = fmaf(s, dA, dt_c * x_c * bc.x);
        float part = s * bc.y;
        part += __shfl_down_sync(0xffffffffu, part, 8, 16);
        part += __shfl_down_sync(0xffffffffu, part, 4, 16);
        part += __shfl_down_sync(0xffffffffu, part, 2, 16);
        part += __shfl_down_sync(0xffffffffu, part, 1, 16);
        if (n == 0) {
            float yv = part + Dsk * x_c;
            yv = yv * (z_c / (1.f + __expf(-z_c)));
            y[(size_t)(t0 + l) * DINNER + d] = __float2half_rn(yv);
        }
    }
}

// ---------------------------------------------------------------------------
extern "C" void kernel_launch(void* const* d_in, const int* in_sizes, int n_in,
                              void* d_out, int out_size)
{
    const float* x      = (const float*)d_in[0];
    const float* ln1_g  = (const float*)d_in[1];
    const float* ln1_b  = (const float*)d_in[2];
    const float* w_in   = (const float*)d_in[3];
    const float* conv_w = (const float*)d_in[4];
    const float* conv_b = (const float*)d_in[5];
    const float* w_x    = (const float*)d_in[6];
    const float* w_dt   = (const float*)d_in[7];
    const float* b_dt   = (const float*)d_in[8];
    const float* a_log  = (const float*)d_in[9];
    const float* d_skip = (const float*)d_in[10];
    const float* w_out  = (const float*)d_in[11];
    const float* ln2_g  = (const float*)d_in[12];
    const float* ln2_b  = (const float*)d_in[13];
    const float* w_ff1  = (const float*)d_in[14];
    const float* b_ff1  = (const float*)d_in[15];
    const float* w_ff2  = (const float*)d_in[16];
    const float* b_ff2  = (const float*)d_in[17];
    float* out = (float*)d_out;

    __half *h, *xch, *dtlo, *y, *h2, *ffa;
    __half *wtin, *wtout, *wtff1, *wtff2, *wxt, *wdtt;
    float *xz, *xc, *dbc, *dtb, *out1, *sf, *sp, *si;
    cudaGetSymbolAddress((void**)&h,     g_h);
    cudaGetSymbolAddress((void**)&xz,    g_xz);
    cudaGetSymbolAddress((void**)&xc,    g_xc);
    cudaGetSymbolAddress((void**)&xch,   g_xch);
    cudaGetSymbolAddress((void**)&dbc,   g_dbc);
    cudaGetSymbolAddress((void**)&dtlo,  g_dtlo);
    cudaGetSymbolAddress((void**)&dtb,   g_dt);
    cudaGetSymbolAddress((void**)&y,     g_y);
    cudaGetSymbolAddress((void**)&out1,  g_out1);
    cudaGetSymbolAddress((void**)&h2,    g_h2);
    cudaGetSymbolAddress((void**)&ffa,   g_ffa);
    cudaGetSymbolAddress((void**)&wtin,  g_wtin);
    cudaGetSymbolAddress((void**)&wtout, g_wtout);
    cudaGetSymbolAddress((void**)&wtff1, g_wtff1);
    cudaGetSymbolAddress((void**)&wtff2, g_wtff2);
    cudaGetSymbolAddress((void**)&wxt,   g_wxt);
    cudaGetSymbolAddress((void**)&wdtt,  g_wdtt);
    cudaGetSymbolAddress((void**)&sf,    g_sf);
    cudaGetSymbolAddress((void**)&sp,    g_sp);
    cudaGetSymbolAddress((void**)&si,    g_si);

    cudaFuncSetAttribute(mh_gemm<0>, cudaFuncAttributeMaxDynamicSharedMemorySize, MH_SMEM);
    cudaFuncSetAttribute(mh_gemm<2>, cudaFuncAttributeMaxDynamicSharedMemorySize, MH_SMEM);
    cudaFuncSetAttribute(mh_gemm<3>, cudaFuncAttributeMaxDynamicSharedMemorySize, MH_SMEM);
    cudaFuncSetAttribute(mh_gemm<5>, cudaFuncAttributeMaxDynamicSharedMemorySize, MH_SMEM);
    cudaFuncSetAttribute(fg_gemm,    cudaFuncAttributeMaxDynamicSharedMemorySize, FG_SMEM);
    cudaFuncSetAttribute(wx_tc,      cudaFuncAttributeMaxDynamicSharedMemorySize, WX_SMEM);

    // 1. all weight transposes in one launch
    transpose_m6<<<18752, 256>>>(
        w_in,  wtin,  1024, 4096, 128, 4096,
        w_out, wtout, 2048, 1024, 32,  6144,
        w_x,   wxt,   2048, 96,   3,   6336,
        w_dt,  wdtt,  64,   2048, 64,  6464,
        w_ff1, wtff1, 1024, 8192, 256, 14656,
        w_ff2, wtff2, 4096, 1024, 32);
    // 2. ln1
    ln_kernel<<<TOKENS, 256>>>(x, ln1_g, ln1_b, h);
    // 3. xz = h @ w_in
    mh_gemm<0><<<dim3(4096 / BN, TOKENS / BM), 256, MH_SMEM>>>(
        h, wtin, xz, nullptr, nullptr, 1024, 4096);
    // 4. conv + silu  [ncu-sampled slot]
    conv_silu_kernel<<<(TOKENS * DINNER) / 256, 256>>>(xz, conv_w, conv_b, xc, xch);
    // 5. dbc = xch @ w_x^T (interleaved B/C) + fp16 dt_lo copy
    wx_tc<<<dim3(1, TOKENS / 64), 256, WX_SMEM>>>(xch, wxt, dbc, dtlo);
    // 6. dt = softplus(dt_lo @ w_dt + b_dt)
    mh_gemm<5><<<dim3(DINNER / BN, TOKENS / BM), 256, MH_SMEM>>>(
        dtlo, wdtt, dtb, b_dt, nullptr, 64, DINNER);
    // 7-9. chunked scan
    scan_partial<<<dim3(4096 / 16, NSEG - 1), 256>>>(dtb, xc, dbc, a_log, sf, sp);
    scan_combine<<<(4096 * DSTATE) / 256, 256>>>(sf, sp, si);
    scan_final<<<dim3(4096 / 16, NSEG), 256>>>(dtb, xc, dbc, xz, a_log, d_skip, si, y);
    // 10. out1 = x + y @ w_out
    mh_gemm<2><<<dim3(DMODEL / BN, TOKENS / BM), 256, MH_SMEM>>>(
        y, wtout, out1, nullptr, x, 2048, DMODEL);
    // 11. ln2
    ln_kernel<<<TOKENS, 256>>>(out1, ln2_g, ln2_b, h2);
    // 12. fused ff1 + geglu
    fg_gemm<<<dim3(FFIN / 64, TOKENS / BM), 256, FG_SMEM>>>(
        h2, wtff1, ffa, b_ff1, 1024);
    // 13. out = out1 + ffa @ w_ff2 + b_ff2
    mh_gemm<3><<<dim3(DMODEL / BN, TOKENS / BM), 256, MH_SMEM>>>(
        ffa, wtff2, out, b_ff2, out1, FFIN, DMODEL);
}

// round 16
// speedup vs baseline: 1.6688x; 1.4969x over previous
#include <cuda_runtime.h>
#include <cuda_fp16.h>
#include <math.h>
#include <stdint.h>

#define TOKENS   4096
#define DMODEL   1024
#define DINNER   2048
#define DSTATE   16
#define DTRANK   64
#define FFIN     4096
#define LSEQ     2048
#define NDBC     128
#define NSEG     16
#define SEGL     128        // LSEQ / NSEG
#define SCH      32         // steps per smem B/C chunk
#define PFD      8

// ---------------- scratch ----------------
__device__ __align__(128) __half g_h    [TOKENS * DMODEL];
__device__ __align__(128) float  g_xz   [TOKENS * 2 * DINNER];
__device__ __align__(128) float  g_xc   [TOKENS * DINNER];
__device__ __align__(128) __half g_xch  [TOKENS * DINNER];
__device__ __align__(128) float  g_dbc  [TOKENS * NDBC];   // cols 64..95: B0,C0,B1,C1,...
__device__ __align__(128) __half g_dtlo [TOKENS * DTRANK];
__device__ __align__(128) float  g_dt   [TOKENS * DINNER];
__device__ __align__(128) __half g_y    [TOKENS * DINNER];
__device__ __align__(128) float  g_out1 [TOKENS * DMODEL];
__device__ __align__(128) __half g_h2   [TOKENS * DMODEL];
__device__ __align__(128) __half g_ffa  [TOKENS * FFIN];
__device__ __align__(128) __half g_wtin [4096 * 1024];
__device__ __align__(128) __half g_wtout[1024 * 2048];
__device__ __align__(128) __half g_wtff1[8192 * 1024];
__device__ __align__(128) __half g_wtff2[1024 * 4096];
__device__ __align__(128) __half g_wxt  [128 * 2048];
__device__ __align__(128) __half g_wdtt [2048 * 64];
// chunked-scan buffers: [seg][gchan][n]
__device__ __align__(128) float  g_sf [(NSEG - 1) * 4096 * DSTATE];
__device__ __align__(128) float  g_sp [(NSEG - 1) * 4096 * DSTATE];
__device__ __align__(128) float  g_si [NSEG * 4096 * DSTATE];

// ---------------- helpers ----------------
__device__ __forceinline__ float softplus_f(float x) {
    return (x > 20.f) ? x : log1pf(expf(x));
}
__device__ __forceinline__ float tanh_ap(float x) {
    float r;
    asm("tanh.approx.f32 %0, %1;" : "=f"(r) : "f"(x));
    return r;
}
__device__ __forceinline__ float gelu_t(float g) {
    float u = 0.7978845608028654f * fmaf(0.044715f * g * g, g, g);
    return 0.5f * g * (1.f + tanh_ap(u));
}
__device__ __forceinline__ uint32_t smem_u32(const void* p) {
    uint32_t a;
    asm("{ .reg .u64 t; cvta.to.shared.u64 t, %1; cvt.u32.u64 %0, t; }" : "=r"(a) : "l"(p));
    return a;
}
__device__ __forceinline__ void cp16(uint32_t dst, const void* src) {
    asm volatile("cp.async.cg.shared.global [%0], [%1], 16;" :: "r"(dst), "l"(src));
}
#define CP_COMMIT() asm volatile("cp.async.commit_group;" ::: "memory")
#define CP_WAIT0()  asm volatile("cp.async.wait_group 0;" ::: "memory")
#define CP_WAIT1()  asm volatile("cp.async.wait_group 1;" ::: "memory")

__device__ __forceinline__ void ldm_x4(uint32_t& r0, uint32_t& r1,
                                       uint32_t& r2, uint32_t& r3, uint32_t addr)
{
    asm volatile("ldmatrix.sync.aligned.m8n8.x4.shared.b16 {%0,%1,%2,%3}, [%4];"
                 : "=r"(r0), "=r"(r1), "=r"(r2), "=r"(r3) : "r"(addr));
}
__device__ __forceinline__ void mma_f16(
    float& c0, float& c1, float& c2, float& c3,
    uint32_t a0, uint32_t a1, uint32_t a2, uint32_t a3,
    uint32_t b0, uint32_t b1)
{
    asm volatile(
        "mma.sync.aligned.m16n8k16.row.col.f32.f16.f16.f32 "
        "{%0,%1,%2,%3}, {%4,%5,%6,%7}, {%8,%9}, {%0,%1,%2,%3};"
        : "+f"(c0), "+f"(c1), "+f"(c2), "+f"(c3)
        : "r"(a0), "r"(a1), "r"(a2), "r"(a3), "r"(b0), "r"(b1));
}

// ---------------------------------------------------------------------------
// fp16 tensor GEMM: C[M,N] = A[M,K] @ Bw[N,K]^T, 128x128 tile, 3-stage pipe.
// MODE bits: 1 = +bias[n], 2 = +res[m,n], 4 = softplus
// ---------------------------------------------------------------------------
#define BM 128
#define BN 128
#define BKH 64
#define LDH 72
#define HSTG ((BM + BN) * LDH)
#define MH_SMEM (3 * HSTG * 2)

__device__ __forceinline__ void mh_load(
    const __half* __restrict__ A, const __half* __restrict__ Bw, int K,
    int m0, int n0, uint32_t sbyte, int stage, int chunk, int tid)
{
    uint32_t ab = sbyte + (uint32_t)stage * (HSTG * 2);
    uint32_t bb = ab + BM * LDH * 2;
    const __half* Ap = A  + (size_t)m0 * K + chunk * BKH;
    const __half* Bp = Bw + (size_t)n0 * K + chunk * BKH;
    #pragma unroll
    for (int p = 0; p < 4; p++) {
        int idx = tid + (p << 8);
        int r = idx >> 3, c = idx & 7;
        cp16(ab + (uint32_t)(r * LDH + c * 8) * 2, Ap + (size_t)r * K + c * 8);
    }
    #pragma unroll
    for (int p = 0; p < 4; p++) {
        int idx = tid + (p << 8);
        int r = idx >> 3, c = idx & 7;
        cp16(bb + (uint32_t)(r * LDH + c * 8) * 2, Bp + (size_t)r * K + c * 8);
    }
}

template <int MODE>
__global__ void __launch_bounds__(256, 2) mh_gemm(
    const __half* __restrict__ A, const __half* __restrict__ Bw,
    float* __restrict__ C, const float* __restrict__ bias,
    const float* __restrict__ res, int K, int N)
{
    extern __shared__ char smraw[];
    const uint32_t sbyte = smem_u32(smraw);
    const int tid  = threadIdx.x;
    const int lane = tid & 31;
    const int wid  = tid >> 5;
    const int wm   = wid >> 1;
    const int wn   = wid & 1;
    const int row  = lane >> 2;
    const int qc   = lane & 3;
    const int m0 = blockIdx.y * BM;
    const int n0 = blockIdx.x * BN;

    const int a_r  = ((lane >> 3) & 1) * 8 + (lane & 7);
    const int a_k  = (lane >> 4) * 8;
    const int b_r  = (lane >> 4) * 8 + (lane & 7);
    const int b_k  = ((lane >> 3) & 1) * 8;

    float acc[2][8][4];
    #pragma unroll
    for (int i = 0; i < 2; i++)
        #pragma unroll
        for (int j = 0; j < 8; j++)
            #pragma unroll
            for (int q = 0; q < 4; q++) acc[i][j][q] = 0.f;

    const int nc = K / BKH;
    mh_load(A, Bw, K, m0, n0, sbyte, 0, 0, tid);
    CP_COMMIT();
    if (1 < nc) mh_load(A, Bw, K, m0, n0, sbyte, 1, 1, tid);
    CP_COMMIT();

    int stage = 0;
    for (int ks = 0; ks < nc; ks++) {
        if (ks + 1 < nc) { CP_WAIT1(); } else { CP_WAIT0(); }
        __syncthreads();
        int ldst = stage + 2; if (ldst >= 3) ldst -= 3;
        if (ks + 2 < nc)
            mh_load(A, Bw, K, m0, n0, sbyte, ldst, ks + 2, tid);
        CP_COMMIT();

        uint32_t as_ = sbyte + (uint32_t)stage * (HSTG * 2);
        uint32_t bs_ = as_ + BM * LDH * 2;
        #pragma unroll
        for (int kk = 0; kk < 4; kk++) {
            int k = kk * 16;
            uint32_t a[2][4];
            #pragma unroll
            for (int mt = 0; mt < 2; mt++) {
                int r = wm * 32 + mt * 16 + a_r;
                ldm_x4(a[mt][0], a[mt][1], a[mt][2], a[mt][3],
                       as_ + (uint32_t)(r * LDH + k + a_k) * 2);
            }
            uint32_t b[8][2];
            #pragma unroll
            for (int q = 0; q < 4; q++) {
                int r = wn * 64 + q * 16 + b_r;
                uint32_t t0, t1, t2, t3;
                ldm_x4(t0, t1, t2, t3,
                       bs_ + (uint32_t)(r * LDH + k + b_k) * 2);
                b[2 * q][0] = t0;  b[2 * q][1] = t1;
                b[2 * q + 1][0] = t2;  b[2 * q + 1][1] = t3;
            }
            #pragma unroll
            for (int mt = 0; mt < 2; mt++)
                #pragma unroll
                for (int nt = 0; nt < 8; nt++)
                    mma_f16(acc[mt][nt][0], acc[mt][nt][1],
                            acc[mt][nt][2], acc[mt][nt][3],
                            a[mt][0], a[mt][1], a[mt][2], a[mt][3],
                            b[nt][0], b[nt][1]);
        }
        stage++; if (stage >= 3) stage -= 3;
    }

    #pragma unroll
    for (int mt = 0; mt < 2; mt++) {
        int gr0 = m0 + wm * 32 + mt * 16 + row;
        #pragma unroll
        for (int nt = 0; nt < 8; nt++) {
            int gc = n0 + wn * 64 + nt * 8 + qc * 2;
            float2 v0 = make_float2(acc[mt][nt][0], acc[mt][nt][1]);
            float2 v1 = make_float2(acc[mt][nt][2], acc[mt][nt][3]);
            if (MODE & 1) {
                float2 bb = *(const float2*)(bias + gc);
                v0.x += bb.x; v0.y += bb.y;
                v1.x += bb.x; v1.y += bb.y;
            }
            if (MODE & 4) {
                v0.x = softplus_f(v0.x); v0.y = softplus_f(v0.y);
                v1.x = softplus_f(v1.x); v1.y = softplus_f(v1.y);
            }
            if (MODE & 2) {
                float2 r0 = *(const float2*)(res + (size_t)gr0 * N + gc);
                float2 r1 = *(const float2*)(res + (size_t)(gr0 + 8) * N + gc);
                v0.x += r0.x; v0.y += r0.y;
                v1.x += r1.x; v1.y += r1.y;
            }
            *(float2*)(C + (size_t)gr0 * N + gc)       = v0;
            *(float2*)(C + (size_t)(gr0 + 8) * N + gc) = v1;
        }
    }
}

// ---------------------------------------------------------------------------
// wx tensor GEMM: dbc[M,128] = xch[M,2048] @ wxt[128,2048]^T (B/C interleaved)
// ---------------------------------------------------------------------------
#define WXSTG ((64 + 128) * LDH)
#define WX_SMEM (2 * WXSTG * 2)

__device__ __forceinline__ void wx_load(
    const __half* __restrict__ A, const __half* __restrict__ Bw,
    int m0, uint32_t sbyte, int stage, int chunk, int tid)
{
    uint32_t ab = sbyte + (uint32_t)stage * (WXSTG * 2);
    uint32_t bb = ab + 64 * LDH * 2;
    const __half* Ap = A  + (size_t)m0 * DINNER + chunk * BKH;
    const __half* Bp = Bw + chunk * BKH;
    #pragma unroll
    for (int p = 0; p < 2; p++) {
        int idx = tid + (p << 8);
        int r = idx >> 3, c = idx & 7;
        cp16(ab + (uint32_t)(r * LDH + c * 8) * 2, Ap + (size_t)r * DINNER + c * 8);
    }
    #pragma unroll
    for (int p = 0; p < 4; p++) {
        int idx = tid + (p << 8);
        int r = idx >> 3, c = idx & 7;
        cp16(bb + (uint32_t)(r * LDH + c * 8) * 2, Bp + (size_t)r * DINNER + c * 8);
    }
}

__device__ __forceinline__ int dbc_col(int c) {
    if (c < 64) return c;
    if (c < 80) return 64 + 2 * (c - 64);       // B_n
    return 64 + 2 * (c - 80) + 1;               // C_n
}

__global__ void __launch_bounds__(256, 2) wx_tc(
    const __half* __restrict__ A, const __half* __restrict__ Bw,
    float* __restrict__ dbc, __half* __restrict__ dtlo)
{
    extern __shared__ char smraw[];
    const uint32_t sbyte = smem_u32(smraw);
    const int tid  = threadIdx.x;
    const int lane = tid & 31;
    const int wid  = tid >> 5;
    const int wm   = wid >> 2;
    const int wn   = wid & 3;
    const int row  = lane >> 2;
    const int qc   = lane & 3;
    const int m0 = blockIdx.y * 64;

    const int a_r  = ((lane >> 3) & 1) * 8 + (lane & 7);
    const int a_k  = (lane >> 4) * 8;
    const int b_r  = (lane >> 4) * 8 + (lane & 7);
    const int b_k  = ((lane >> 3) & 1) * 8;

    float acc[2][4][4];
    #pragma unroll
    for (int i = 0; i < 2; i++)
        #pragma unroll
        for (int j = 0; j < 4; j++)
            #pragma unroll
            for (int q = 0; q < 4; q++) acc[i][j][q] = 0.f;

    const int nc = DINNER / BKH;
    wx_load(A, Bw, m0, sbyte, 0, 0, tid);
    CP_COMMIT();

    for (int ks = 0; ks < nc; ks++) {
        if (ks + 1 < nc) {
            wx_load(A, Bw, m0, sbyte, (ks + 1) & 1, ks + 1, tid);
            CP_COMMIT();
            CP_WAIT1();
        } else {
            CP_WAIT0();
        }
        __syncthreads();

        uint32_t as_ = sbyte + (uint32_t)(ks & 1) * (WXSTG * 2);
        uint32_t bs_ = as_ + 64 * LDH * 2;
        #pragma unroll
        for (int kk = 0; kk < 4; kk++) {
            int k = kk * 16;
            uint32_t a[2][4];
            #pragma unroll
            for (int mt = 0; mt < 2; mt++) {
                int r = wm * 32 + mt * 16 + a_r;
                ldm_x4(a[mt][0], a[mt][1], a[mt][2], a[mt][3],
                       as_ + (uint32_t)(r * LDH + k + a_k) * 2);
            }
            uint32_t b[4][2];
            #pragma unroll
            for (int q = 0; q < 2; q++) {
                int r = wn * 32 + q * 16 + b_r;
                uint32_t t0, t1, t2, t3;
                ldm_x4(t0, t1, t2, t3, bs_ + (uint32_t)(r * LDH + k + b_k) * 2);
                b[2 * q][0] = t0;  b[2 * q][1] = t1;
                b[2 * q + 1][0] = t2;  b[2 * q + 1][1] = t3;
            }
            #pragma unroll
            for (int mt = 0; mt < 2; mt++)
                #pragma unroll
                for (int nt = 0; nt < 4; nt++)
                    mma_f16(acc[mt][nt][0], acc[mt][nt][1],
                            acc[mt][nt][2], acc[mt][nt][3],
                            a[mt][0], a[mt][1], a[mt][2], a[mt][3],
                            b[nt][0], b[nt][1]);
        }
        __syncthreads();
    }

    #pragma unroll
    for (int mt = 0; mt < 2; mt++) {
        int gr0 = m0 + wm * 32 + mt * 16 + row;
        #pragma unroll
        for (int nt = 0; nt < 4; nt++) {
            int gc = wn * 32 + nt * 8 + qc * 2;
            float2 v0 = make_float2(acc[mt][nt][0], acc[mt][nt][1]);
            float2 v1 = make_float2(acc[mt][nt][2], acc[mt][nt][3]);
            dbc[(size_t)gr0 * NDBC + dbc_col(gc)]           = v0.x;
            dbc[(size_t)gr0 * NDBC + dbc_col(gc + 1)]       = v0.y;
            dbc[(size_t)(gr0 + 8) * NDBC + dbc_col(gc)]     = v1.x;
            dbc[(size_t)(gr0 + 8) * NDBC + dbc_col(gc + 1)] = v1.y;
            if (gc < DTRANK) {
                ((__half2*)(dtlo + (size_t)gr0 * DTRANK))[gc >> 1] =
                    __floats2half2_rn(v0.x, v0.y);
                ((__half2*)(dtlo + (size_t)(gr0 + 8) * DTRANK))[gc >> 1] =
                    __floats2half2_rn(v1.x, v1.y);
            }
        }
    }
}

// ---------------------------------------------------------------------------
// Fused ff1 + geglu, 128x64 tile, 3-stage pipeline
// ---------------------------------------------------------------------------
#define FG_SMEM MH_SMEM

__device__ __forceinline__ void fg_load(
    const __half* __restrict__ A, const __half* __restrict__ Bw, int K,
    int m0, int n0, uint32_t sbyte, int stage, int chunk, int tid)
{
    uint32_t ab  = sbyte + (uint32_t)stage * (HSTG * 2);
    uint32_t bab = ab  + BM * LDH * 2;
    uint32_t bgb = bab + 64 * LDH * 2;
    const __half* Ap  = A  + (size_t)m0 * K + chunk * BKH;
    const __half* Bap = Bw + (size_t)n0 * K + chunk * BKH;
    const __half* Bgp = Bw + (size_t)(4096 + n0) * K + chunk * BKH;
    #pragma unroll
    for (int p = 0; p < 4; p++) {
        int idx = tid + (p << 8);
        int r = idx >> 3, c = idx & 7;
        cp16(ab + (uint32_t)(r * LDH + c * 8) * 2, Ap + (size_t)r * K + c * 8);
    }
    #pragma unroll
    for (int p = 0; p < 2; p++) {
        int idx = tid + (p << 8);
        int r = idx >> 3, c = idx & 7;
        cp16(bab + (uint32_t)(r * LDH + c * 8) * 2, Bap + (size_t)r * K + c * 8);
    }
    #pragma unroll
    for (int p = 0; p < 2; p++) {
        int idx = tid + (p << 8);
        int r = idx >> 3, c = idx & 7;
        cp16(bgb + (uint32_t)(r * LDH + c * 8) * 2, Bgp + (size_t)r * K + c * 8);
    }
}

__global__ void __launch_bounds__(256, 2) fg_gemm(
    const __half* __restrict__ A, const __half* __restrict__ Bw,
    __half* __restrict__ out, const float* __restrict__ bias, int K)
{
    extern __shared__ char smraw[];
    const uint32_t sbyte = smem_u32(smraw);
    const int tid  = threadIdx.x;
    const int lane = tid & 31;
    const int wid  = tid >> 5;
    const int wm   = wid >> 1;
    const int wn   = wid & 1;
    const int row  = lane >> 2;
    const int qc   = lane & 3;
    const int m0 = blockIdx.y * BM;
    const int n0 = blockIdx.x * 64;

    const int a_r  = ((lane >> 3) & 1) * 8 + (lane & 7);
    const int a_k  = (lane >> 4) * 8;
    const int b_r  = (lane >> 4) * 8 + (lane & 7);
    const int b_k  = ((lane >> 3) & 1) * 8;

    float acca[2][4][4], accg[2][4][4];
    #pragma unroll
    for (int i = 0; i < 2; i++)
        #pragma unroll
        for (int j = 0; j < 4; j++)
            #pragma unroll
            for (int q = 0; q < 4; q++) { acca[i][j][q] = 0.f; accg[i][j][q] = 0.f; }

    const int nc = K / BKH;
    fg_load(A, Bw, K, m0, n0, sbyte, 0, 0, tid);
    CP_COMMIT();
    if (1 < nc) fg_load(A, Bw, K, m0, n0, sbyte, 1, 1, tid);
    CP_COMMIT();

    int stage = 0;
    for (int ks = 0; ks < nc; ks++) {
        if (ks + 1 < nc) { CP_WAIT1(); } else { CP_WAIT0(); }
        __syncthreads();
        int ldst = stage + 2; if (ldst >= 3) ldst -= 3;
        if (ks + 2 < nc)
            fg_load(A, Bw, K, m0, n0, sbyte, ldst, ks + 2, tid);
        CP_COMMIT();

        uint32_t as_ = sbyte + (uint32_t)stage * (HSTG * 2);
        uint32_t ba_ = as_ + BM * LDH * 2;
        uint32_t bg_ = ba_ + 64 * LDH * 2;
        #pragma unroll
        for (int kk = 0; kk < 4; kk++) {
            int k = kk * 16;
            uint32_t a[2][4];
            #pragma unroll
            for (int mt = 0; mt < 2; mt++) {
                int r = wm * 32 + mt * 16 + a_r;
                ldm_x4(a[mt][0], a[mt][1], a[mt][2], a[mt][3],
                       as_ + (uint32_t)(r * LDH + k + a_k) * 2);
            }
            uint32_t ba[4][2], bg[4][2];
            #pragma unroll
            for (int q = 0; q < 2; q++) {
                int r = wn * 32 + q * 16 + b_r;
                uint32_t t0, t1, t2, t3;
                ldm_x4(t0, t1, t2, t3, ba_ + (uint32_t)(r * LDH + k + b_k) * 2);
                ba[2 * q][0] = t0;  ba[2 * q][1] = t1;
                ba[2 * q + 1][0] = t2;  ba[2 * q + 1][1] = t3;
                ldm_x4(t0, t1, t2, t3, bg_ + (uint32_t)(r * LDH + k + b_k) * 2);
                bg[2 * q][0] = t0;  bg[2 * q][1] = t1;
                bg[2 * q + 1][0] = t2;  bg[2 * q + 1][1] = t3;
            }
            #pragma unroll
            for (int mt = 0; mt < 2; mt++)
                #pragma unroll
                for (int nt = 0; nt < 4; nt++) {
                    mma_f16(acca[mt][nt][0], acca[mt][nt][1],
                            acca[mt][nt][2], acca[mt][nt][3],
                            a[mt][0], a[mt][1], a[mt][2], a[mt][3],
                            ba[nt][0], ba[nt][1]);
                    mma_f16(accg[mt][nt][0], accg[mt][nt][1],
                            accg[mt][nt][2], accg[mt][nt][3],
                            a[mt][0], a[mt][1], a[mt][2], a[mt][3],
                            bg[nt][0], bg[nt][1]);
                }
        }
        stage++; if (stage >= 3) stage -= 3;
    }

    #pragma unroll
    for (int mt = 0; mt < 2; mt++) {
        int gr0 = m0 + wm * 32 + mt * 16 + row;
        #pragma unroll
        for (int nt = 0; nt < 4; nt++) {
            int gc = n0 + wn * 32 + nt * 8 + qc * 2;
            float2 bba = *(const float2*)(bias + gc);
            float2 bbg = *(const float2*)(bias + 4096 + gc);
            float a0 = acca[mt][nt][0] + bba.x, a1 = acca[mt][nt][1] + bba.y;
            float g0 = accg[mt][nt][0] + bbg.x, g1 = accg[mt][nt][1] + bbg.y;
            float a2 = acca[mt][nt][2] + bba.x, a3 = acca[mt][nt][3] + bba.y;
            float g2 = accg[mt][nt][2] + bbg.x, g3 = accg[mt][nt][3] + bbg.y;
            ((__half2*)(out + (size_t)gr0 * FFIN))[gc >> 1] =
                __floats2half2_rn(a0 * gelu_t(g0), a1 * gelu_t(g1));
            ((__half2*)(out + (size_t)(gr0 + 8) * FFIN))[gc >> 1] =
                __floats2half2_rn(a2 * gelu_t(g2), a3 * gelu_t(g3));
        }
    }
}

// ---------------------------------------------------------------------------
// 6-segment transpose fp32[K,N] -> fp16[N,K]
// ---------------------------------------------------------------------------
__global__ void __launch_bounds__(256) transpose_m6(
    const float* in0, __half* out0, int K0, int N0, int gx0, int c1,
    const float* in1, __half* out1, int K1, int N1, int gx1, int c2,
    const float* in2, __half* out2, int K2, int N2, int gx2, int c3,
    const float* in3, __half* out3, int K3, int N3, int gx3, int c4,
    const float* in4, __half* out4, int K4, int N4, int gx4, int c5,
    const float* in5, __half* out5, int K5, int N5, int gx5)
{
    int b = blockIdx.x;
    const float* in; __half* out; int K, N, gx, local;
    if (b < c1)      { in = in0; out = out0; K = K0; N = N0; gx = gx0; local = b; }
    else if (b < c2) { in = in1; out = out1; K = K1; N = N1; gx = gx1; local = b - c1; }
    else if (b < c3) { in = in2; out = out2; K = K2; N = N2; gx = gx2; local = b - c2; }
    else if (b < c4) { in = in3; out = out3; K = K3; N = N3; gx = gx3; local = b - c3; }
    else if (b < c5) { in = in4; out = out4; K = K4; N = N4; gx = gx4; local = b - c4; }
    else             { in = in5; out = out5; K = K5; N = N5; gx = gx5; local = b - c5; }
    int n0 = (local % gx) * 32;
    int k0 = (local / gx) * 32;

    __shared__ float t[32][33];
    int x = threadIdx.x & 31, y = threadIdx.x >> 5;
    #pragma unroll
    for (int i = 0; i < 4; i++)
        t[y + 8 * i][x] = in[(size_t)(k0 + y + 8 * i) * N + n0 + x];
    __syncthreads();
    #pragma unroll
    for (int i = 0; i < 4; i++)
        out[(size_t)(n0 + y + 8 * i) * K + k0 + x] = __float2half_rn(t[x][y + 8 * i]);
}

// ---------------------------------------------------------------------------
__global__ void __launch_bounds__(256) ln_kernel(
    const float* __restrict__ x, const float* __restrict__ g,
    const float* __restrict__ b, __half* __restrict__ out)
{
    int t = blockIdx.x, tid = threadIdx.x;
    float4 v = ((const float4*)(x + (size_t)t * DMODEL))[tid];
    float s  = v.x + v.y + v.z + v.w;
    float ss = fmaf(v.x, v.x, fmaf(v.y, v.y, fmaf(v.z, v.z, v.w * v.w)));
    #pragma unroll
    for (int o = 16; o > 0; o >>= 1) {
        s  += __shfl_down_sync(0xffffffffu, s, o);
        ss += __shfl_down_sync(0xffffffffu, ss, o);
    }
    __shared__ float rs_[8], rss_[8];
    __shared__ float smu, srs;
    int warp = tid >> 5, lane = tid & 31;
    if (lane == 0) { rs_[warp] = s; rss_[warp] = ss; }
    __syncthreads();
    if (tid == 0) {
        float S = 0.f, SS = 0.f;
        #pragma unroll
        for (int w = 0; w < 8; w++) { S += rs_[w]; SS += rss_[w]; }
        float mu = S * (1.f / DMODEL);
        smu = mu;
        srs = rsqrtf(SS * (1.f / DMODEL) - mu * mu + 1e-5f);
    }
    __syncthreads();
    float mu = smu, rs = srs;
    float4 gv = ((const float4*)g)[tid];
    float4 bv = ((const float4*)b)[tid];
    __half2 p0 = __floats2half2_rn((v.x - mu) * rs * gv.x + bv.x,
                                   (v.y - mu) * rs * gv.y + bv.y);
    __half2 p1 = __floats2half2_rn((v.z - mu) * rs * gv.z + bv.z,
                                   (v.w - mu) * rs * gv.w + bv.w);
    __half2* orow = (__half2*)(out + (size_t)t * DMODEL);
    orow[2 * tid]     = p0;
    orow[2 * tid + 1] = p1;
}

// ---------------------------------------------------------------------------
// conv + silu: fp32 out (scan) + fp16 out (wx GEMM)
// ---------------------------------------------------------------------------
__global__ void __launch_bounds__(256) conv_silu_kernel(
    const float* __restrict__ xz, const float* __restrict__ w,
    const float* __restrict__ cb, float* __restrict__ out,
    __half* __restrict__ outh)
{
    int idx = blockIdx.x * 256 + threadIdx.x;
    int d = idx & (DINNER - 1);
    int t = idx >> 11;
    int l = t & (LSEQ - 1);
    float w0 = w[d * 4 + 0], w1 = w[d * 4 + 1], w2 = w[d * 4 + 2], w3 = w[d * 4 + 3];
    float s = cb[d];
    const float* base = xz + (size_t)t * (2 * DINNER) + d;
    if (l >= 3) s = fmaf(w0, base[-3 * (ptrdiff_t)(2 * DINNER)], s);
    if (l >= 2) s = fmaf(w1, base[-2 * (ptrdiff_t)(2 * DINNER)], s);
    if (l >= 1) s = fmaf(w2, base[-1 * (ptrdiff_t)(2 * DINNER)], s);
    s = fmaf(w3, base[0], s);
    float r = s / (1.f + expf(-s));
    out[idx]  = r;
    outh[idx] = __float2half_rn(r);
}

// ---------------------------------------------------------------------------
// chunked selective scan, thread-per-channel (16 states in registers).
// B/C staged to SMEM per 32-step chunk (broadcast reads).
// ---------------------------------------------------------------------------
// pass A: per-segment local scan (init 0): f[16], p[16]=prod(dA)
__global__ void __launch_bounds__(256) scan_partial(
    const float* __restrict__ dt, const float* __restrict__ xc,
    const float* __restrict__ dbc, const float* __restrict__ a_log,
    float* __restrict__ sf, float* __restrict__ sp)
{
    __shared__ float sbc[2][SCH * 32];
    int seg = blockIdx.y;                        // 0..NSEG-2
    int tid = threadIdx.x;
    int gchan = blockIdx.x * 256 + tid;
    int b = gchan >> 11;
    int d = gchan & (DINNER - 1);
    int t0 = b * LSEQ + seg * SEGL;

    float Ac[16];
    #pragma unroll
    for (int q = 0; q < 4; q++) {
        float4 v = *(const float4*)(a_log + (size_t)d * DSTATE + q * 4);
        Ac[q * 4 + 0] = -expf(v.x);
        Ac[q * 4 + 1] = -expf(v.y);
        Ac[q * 4 + 2] = -expf(v.z);
        Ac[q * 4 + 3] = -expf(v.w);
    }

    float s[16], p[16];
    #pragma unroll
    for (int n = 0; n < 16; n++) { s[n] = 0.f; p[n] = 1.f; }

    float dtb[PFD], xb[PFD];
    #pragma unroll
    for (int i = 0; i < PFD; i++) {
        dtb[i] = dt[(size_t)(t0 + i) * DINNER + d];
        xb [i] = xc[(size_t)(t0 + i) * DINNER + d];
    }

    // stage chunk 0 (thread -> 16B: step = tid/8, part = tid%8)
    {
        int st = tid >> 3, pt = tid & 7;
        cp16(smem_u32(&sbc[0][st * 32 + pt * 4]),
             dbc + (size_t)(t0 + st) * NDBC + 64 + pt * 4);
    }
    CP_COMMIT();

    const int nch = SEGL / SCH;
    for (int c = 0; c < nch; c++) {
        CP_WAIT0();
        __syncthreads();
        if (c + 1 < nch) {
            int st = tid >> 3, pt = tid & 7;
            cp16(smem_u32(&sbc[(c + 1) & 1][st * 32 + pt * 4]),
                 dbc + (size_t)(t0 + (c + 1) * SCH + st) * NDBC + 64 + pt * 4);
        }
        CP_COMMIT();

        #pragma unroll 8
        for (int l = 0; l < SCH; l++) {
            int gl = c * SCH + l;
            int bi = gl & (PFD - 1);
            float dt_c = dtb[bi], x_c = xb[bi];
            int lp = gl + PFD;
            if (lp < SEGL) {
                dtb[bi] = dt[(size_t)(t0 + lp) * DINNER + d];
                xb [bi] = xc[(size_t)(t0 + lp) * DINNER + d];
            }
            float u = dt_c * x_c;
            const float2* bc = (const float2*)&sbc[c & 1][l * 32];
            #pragma unroll
            for (int n = 0; n < 16; n++) {
                float dA = __expf(dt_c * Ac[n]);
                p[n] *= dA;
                s[n] = fmaf(s[n], dA, u * bc[n].x);
            }
        }
    }

    size_t o = ((size_t)seg * 4096 + gchan) * DSTATE;
    #pragma unroll
    for (int q = 0; q < 4; q++) {
        *(float4*)(sf + o + q * 4) =
            make_float4(s[q * 4], s[q * 4 + 1], s[q * 4 + 2], s[q * 4 + 3]);
        *(float4*)(sp + o + q * 4) =
            make_float4(p[q * 4], p[q * 4 + 1], p[q * 4 + 2], p[q * 4 + 3]);
    }
}

// pass B: sequential combine across segments
__global__ void __launch_bounds__(256) scan_combine(
    const float* __restrict__ sf, const float* __restrict__ sp,
    float* __restrict__ si)
{
    int idx = blockIdx.x * 256 + threadIdx.x;    // < 4096*16
    float s = 0.f;
    #pragma unroll
    for (int seg = 0; seg < NSEG; seg++) {
        si[(size_t)seg * (4096 * DSTATE) + idx] = s;
        if (seg < NSEG - 1)
            s = fmaf(sp[(size_t)seg * (4096 * DSTATE) + idx], s,
                     sf[(size_t)seg * (4096 * DSTATE) + idx]);
    }
}

// pass C: per-segment scan with correct init; full fused epilogue
__global__ void __launch_bounds__(256) scan_final(
    const float* __restrict__ dt, const float* __restrict__ xc,
    const float* __restrict__ dbc, const float* __restrict__ xz,
    const float* __restrict__ a_log, const float* __restrict__ d_skip,
    const float* __restrict__ si, __half* __restrict__ y)
{
    __shared__ float sbc[2][SCH * 32];
    int seg = blockIdx.y;                        // 0..NSEG-1
    int tid = threadIdx.x;
    int gchan = blockIdx.x * 256 + tid;
    int b = gchan >> 11;
    int d = gchan & (DINNER - 1);
    int t0 = b * LSEQ + seg * SEGL;
    float Dsk = d_skip[d];

    float Ac[16];
    #pragma unroll
    for (int q = 0; q < 4; q++) {
        float4 v = *(const float4*)(a_log + (size_t)d * DSTATE + q * 4);
        Ac[q * 4 + 0] = -expf(v.x);
        Ac[q * 4 + 1] = -expf(v.y);
        Ac[q * 4 + 2] = -expf(v.z);
        Ac[q * 4 + 3] = -expf(v.w);
    }

    float s[16];
    {
        size_t o = ((size_t)seg * 4096 + gchan) * DSTATE;
        #pragma unroll
        for (int q = 0; q < 4; q++) {
            float4 v = *(const float4*)(si + o + q * 4);
            s[q * 4 + 0] = v.x; s[q * 4 + 1] = v.y;
            s[q * 4 + 2] = v.z; s[q * 4 + 3] = v.w;
        }
    }

    float dtb[PFD], xb[PFD], zb[PFD];
    #pragma unroll
    for (int i = 0; i < PFD; i++) {
        dtb[i] = dt[(size_t)(t0 + i) * DINNER + d];
        xb [i] = xc[(size_t)(t0 + i) * DINNER + d];
        zb [i] = xz[(size_t)(t0 + i) * (2 * DINNER) + DINNER + d];
    }

    {
        int st = tid >> 3, pt = tid & 7;
        cp16(smem_u32(&sbc[0][st * 32 + pt * 4]),
             dbc + (size_t)(t0 + st) * NDBC + 64 + pt * 4);
    }
    CP_COMMIT();

    const int nch = SEGL / SCH;
    for (int c = 0; c < nch; c++) {
        CP_WAIT0();
        __syncthreads();
        if (c + 1 < nch) {
            int st = tid >> 3, pt = tid & 7;
            cp16(smem_u32(&sbc[(c + 1) & 1][st * 32 + pt * 4]),
                 dbc + (size_t)(t0 + (c + 1) * SCH + st) * NDBC + 64 + pt * 4);
        }
        CP_COMMIT();

        #pragma unroll 8
        for (int l = 0; l < SCH; l++) {
            int gl = c * SCH + l;
            int bi = gl & (PFD - 1);
            float dt_c = dtb[bi], x_c = xb[bi], z_c = zb[bi];
            int lp = gl + PFD;
            if (lp < SEGL) {
                dtb[bi] = dt[(size_t)(t0 + lp) * DINNER + d];
                xb [bi] = xc[(size_t)(t0 + lp) * DINNER + d];
                zb [bi] = xz[(size_t)(t0 + lp) * (2 * DINNER) + DINNER + d];
            }
            float u = dt_c * x_c;
            const float2* bc = (const float2*)&sbc[c & 1][l * 32];
            float acc = 0.f;
            #pragma unroll
            for (int n = 0; n < 16; n++) {
                float dA = __expf(dt_c * Ac[n]);
                s[n] = fmaf(s[n], dA, u * bc[n].x);
                acc = fmaf(s[n], bc[n].y, acc);
            }
            float yv = acc + Dsk * x_c;
            yv = yv * (z_c / (1.f + __expf(-z_c)));
            y[(size_t)(t0 + gl) * DINNER + d] = __float2half_rn(yv);
        }
    }
}

// ---------------------------------------------------------------------------
extern "C" void kernel_launch(void* const* d_in, const int* in_sizes, int n_in,
                              void* d_out, int out_size)
{
    const float* x      = (const float*)d_in[0];
    const float* ln1_g  = (const float*)d_in[1];
    const float* ln1_b  = (const float*)d_in[2];
    const float* w_in   = (const float*)d_in[3];
    const float* conv_w = (const float*)d_in[4];
    const float* conv_b = (const float*)d_in[5];
    const float* w_x    = (const float*)d_in[6];
    const float* w_dt   = (const float*)d_in[7];
    const float* b_dt   = (const float*)d_in[8];
    const float* a_log  = (const float*)d_in[9];
    const float* d_skip = (const float*)d_in[10];
    const float* w_out  = (const float*)d_in[11];
    const float* ln2_g  = (const float*)d_in[12];
    const float* ln2_b  = (const float*)d_in[13];
    const float* w_ff1  = (const float*)d_in[14];
    const float* b_ff1  = (const float*)d_in[15];
    const float* w_ff2  = (const float*)d_in[16];
    const float* b_ff2  = (const float*)d_in[17];
    float* out = (float*)d_out;

    __half *h, *xch, *dtlo, *y, *h2, *ffa;
    __half *wtin, *wtout, *wtff1, *wtff2, *wxt, *wdtt;
    float *xz, *xc, *dbc, *dtb, *out1, *sf, *sp, *si;
    cudaGetSymbolAddress((void**)&h,     g_h);
    cudaGetSymbolAddress((void**)&xz,    g_xz);
    cudaGetSymbolAddress((void**)&xc,    g_xc);
    cudaGetSymbolAddress((void**)&xch,   g_xch);
    cudaGetSymbolAddress((void**)&dbc,   g_dbc);
    cudaGetSymbolAddress((void**)&dtlo,  g_dtlo);
    cudaGetSymbolAddress((void**)&dtb,   g_dt);
    cudaGetSymbolAddress((void**)&y,     g_y);
    cudaGetSymbolAddress((void**)&out1,  g_out1);
    cudaGetSymbolAddress((void**)&h2,    g_h2);
    cudaGetSymbolAddress((void**)&ffa,   g_ffa);
    cudaGetSymbolAddress((void**)&wtin,  g_wtin);
    cudaGetSymbolAddress((void**)&wtout, g_wtout);
    cudaGetSymbolAddress((void**)&wtff1, g_wtff1);
    cudaGetSymbolAddress((void**)&wtff2, g_wtff2);
    cudaGetSymbolAddress((void**)&wxt,   g_wxt);
    cudaGetSymbolAddress((void**)&wdtt,  g_wdtt);
    cudaGetSymbolAddress((void**)&sf,    g_sf);
    cudaGetSymbolAddress((void**)&sp,    g_sp);
    cudaGetSymbolAddress((void**)&si,    g_si);

    cudaFuncSetAttribute(mh_gemm<0>, cudaFuncAttributeMaxDynamicSharedMemorySize, MH_SMEM);
    cudaFuncSetAttribute(mh_gemm<2>, cudaFuncAttributeMaxDynamicSharedMemorySize, MH_SMEM);
    cudaFuncSetAttribute(mh_gemm<3>, cudaFuncAttributeMaxDynamicSharedMemorySize, MH_SMEM);
    cudaFuncSetAttribute(mh_gemm<5>, cudaFuncAttributeMaxDynamicSharedMemorySize, MH_SMEM);
    cudaFuncSetAttribute(fg_gemm,    cudaFuncAttributeMaxDynamicSharedMemorySize, FG_SMEM);
    cudaFuncSetAttribute(wx_tc,      cudaFuncAttributeMaxDynamicSharedMemorySize, WX_SMEM);

    // 1. all weight transposes in one launch
    transpose_m6<<<18752, 256>>>(
        w_in,  wtin,  1024, 4096, 128, 4096,
        w_out, wtout, 2048, 1024, 32,  6144,
        w_x,   wxt,   2048, 96,   3,   6336,
        w_dt,  wdtt,  64,   2048, 64,  6464,
        w_ff1, wtff1, 1024, 8192, 256, 14656,
        w_ff2, wtff2, 4096, 1024, 32);
    // 2. ln1
    ln_kernel<<<TOKENS, 256>>>(x, ln1_g, ln1_b, h);
    // 3. xz = h @ w_in
    mh_gemm<0><<<dim3(4096 / BN, TOKENS / BM), 256, MH_SMEM>>>(
        h, wtin, xz, nullptr, nullptr, 1024, 4096);
    // 4. conv + silu  [ncu-sampled slot]
    conv_silu_kernel<<<(TOKENS * DINNER) / 256, 256>>>(xz, conv_w, conv_b, xc, xch);
    // 5. dbc = xch @ w_x^T (interleaved B/C) + fp16 dt_lo copy
    wx_tc<<<dim3(1, TOKENS / 64), 256, WX_SMEM>>>(xch, wxt, dbc, dtlo);
    // 6. dt = softplus(dt_lo @ w_dt + b_dt)
    mh_gemm<5><<<dim3(DINNER / BN, TOKENS / BM), 256, MH_SMEM>>>(
        dtlo, wdtt, dtb, b_dt, nullptr, 64, DINNER);
    // 7-9. chunked scan (thread-per-channel)
    scan_partial<<<dim3(4096 / 256, NSEG - 1), 256>>>(dtb, xc, dbc, a_log, sf, sp);
    scan_combine<<<(4096 * DSTATE) / 256, 256>>>(sf, sp, si);
    scan_final<<<dim3(4096 / 256, NSEG), 256>>>(dtb, xc, dbc, xz, a_log, d_skip, si, y);
    // 10. out1 = x + y @ w_out
    mh_gemm<2><<<dim3(DMODEL / BN, TOKENS / BM), 256, MH_SMEM>>>(
        y, wtout, out1, nullptr, x, 2048, DMODEL);
    // 11. ln2
    ln_kernel<<<TOKENS, 256>>>(out1, ln2_g, ln2_b, h2);
    // 12. fused ff1 + geglu
    fg_gemm<<<dim3(FFIN / 64, TOKENS / BM), 256, FG_SMEM>>>(
        h2, wtff1, ffa, b_ff1, 1024);
    // 13. out = out1 + ffa @ w_ff2 + b_ff2
    mh_gemm<3><<<dim3(DMODEL / BN, TOKENS / BM), 256, MH_SMEM>>>(
        ffa, wtff2, out, b_ff2, out1, FFIN, DMODEL);
}